// round 4
// baseline (speedup 1.0000x reference)
#include <cuda_runtime.h>
#include <math.h>

#define N_NODES 50000
#define N_EDGES 800000
#define F_DIM   128
#define OUT_DIM 256

// ---------------- device scratch (no allocations allowed) ----------------
__device__ float    g_bufA[(size_t)N_NODES * F_DIM];   // agg output
__device__ float    g_bufB[(size_t)N_NODES * F_DIM];   // hidden h1
__device__ int      g_cnt[N_NODES];
__device__ int      g_rowptr[N_NODES + 1];
__device__ int      g_cursor[N_NODES];
__device__ int      g_col[N_EDGES];
__device__ float    g_dinv[N_NODES];
__device__ float    g_logits[N_NODES];
__device__ unsigned g_max_enc;
__device__ float    g_wsum;
__device__ float    g_gacc[OUT_DIM];
__device__ int      g_is64;

// ---------------- helpers ----------------
__device__ __forceinline__ int edge_src(const void* ei, int e) {
    return g_is64 ? (int)((const long long*)ei)[e] : ((const int*)ei)[e];
}
__device__ __forceinline__ int edge_dst(const void* ei, int e) {
    return g_is64 ? (int)((const long long*)ei)[(size_t)N_EDGES + e]
                  : ((const int*)ei)[(size_t)N_EDGES + e];
}

// ---------------- init ----------------
__global__ void k_init() {
    int i = blockIdx.x * blockDim.x + threadIdx.x;
    int stride = gridDim.x * blockDim.x;
    for (int j = i; j < N_NODES; j += stride) { g_cnt[j] = 0; g_cursor[j] = 0; }
    if (i < OUT_DIM) g_gacc[i] = 0.f;
    if (i == 0) { g_wsum = 0.f; g_max_enc = 0u; }
}

// detect int64 vs int32 edge_index: int64 values <50000 have zero high words
__global__ void k_detect(const int* p) {
    if (threadIdx.x == 0 && blockIdx.x == 0) {
        int ornz = 0;
        #pragma unroll 8
        for (int i = 0; i < 256; i++) ornz |= p[2 * i + 1];
        g_is64 = (ornz == 0) ? 1 : 0;
    }
}

// ---------------- degree histogram ----------------
__global__ void k_count(const void* __restrict__ ei) {
    int e = blockIdx.x * blockDim.x + threadIdx.x;
    if (e >= N_EDGES) return;
    atomicAdd(&g_cnt[edge_dst(ei, e)], 1);
}

__global__ void k_dinv() {
    int i = blockIdx.x * blockDim.x + threadIdx.x;
    if (i < N_NODES) g_dinv[i] = rsqrtf((float)(g_cnt[i] + 1));  // +1 self-loop
}

// single-block exclusive scan of g_cnt -> g_rowptr
__global__ void k_scan() {
    __shared__ int sh[1024];
    const int t = threadIdx.x;
    const int CH = (N_NODES + 1023) / 1024;  // 49
    int start = t * CH;
    int sum = 0;
    for (int i = 0; i < CH; i++) {
        int idx = start + i;
        if (idx < N_NODES) sum += g_cnt[idx];
    }
    sh[t] = sum;
    __syncthreads();
    for (int off = 1; off < 1024; off <<= 1) {
        int v = (t >= off) ? sh[t - off] : 0;
        __syncthreads();
        sh[t] += v;
        __syncthreads();
    }
    int run = sh[t] - sum;  // exclusive prefix
    for (int i = 0; i < CH; i++) {
        int idx = start + i;
        if (idx < N_NODES) { g_rowptr[idx] = run; run += g_cnt[idx]; }
    }
    if (t == 1023) g_rowptr[N_NODES] = run;  // == N_EDGES
}

__global__ void k_fill(const void* __restrict__ ei) {
    int e = blockIdx.x * blockDim.x + threadIdx.x;
    if (e >= N_EDGES) return;
    int s = edge_src(ei, e);
    int d = edge_dst(ei, e);
    int pos = g_rowptr[d] + atomicAdd(&g_cursor[d], 1);
    g_col[pos] = s;
}

// ---------------- GCN aggregation: out[i] = dinv[i]*(sum dinv[s]*in[s]) + dinv[i]^2*in[i]
// one warp per node, float4 per lane (128 floats/row)
__global__ void k_agg(const float* __restrict__ in, float* __restrict__ out) {
    int node = (blockIdx.x * blockDim.x + threadIdx.x) >> 5;
    if (node >= N_NODES) return;
    int lane = threadIdx.x & 31;
    const float4* inv = reinterpret_cast<const float4*>(in);
    float di = g_dinv[node];
    float4 v = inv[(size_t)node * 32 + lane];
    float sw = di * di;
    float4 acc = make_float4(v.x * sw, v.y * sw, v.z * sw, v.w * sw);
    int beg = g_rowptr[node], end = g_rowptr[node + 1];
    int p = beg;
    int s_next = (p < end) ? g_col[p] : 0;
    for (; p < end; ++p) {
        int s = s_next;
        if (p + 1 < end) s_next = g_col[p + 1];
        float w = g_dinv[s] * di;
        float4 u = inv[(size_t)s * 32 + lane];
        acc.x = fmaf(u.x, w, acc.x);
        acc.y = fmaf(u.y, w, acc.y);
        acc.z = fmaf(u.z, w, acc.z);
        acc.w = fmaf(u.w, w, acc.w);
    }
    reinterpret_cast<float4*>(out)[(size_t)node * 32 + lane] = acc;
}

// ---------------- SGEMM 128x128 tile, K=128, fused bias+relu ----------------
__global__ __launch_bounds__(256) void k_gemm_bias_relu(
    const float* __restrict__ A, const float* __restrict__ B,
    const float* __restrict__ bias, float* __restrict__ C, int M, int N) {
    const int K = 128;
    __shared__ float As[8][128];
    __shared__ float Bs[8][128];
    int t = threadIdx.x;
    int row0 = blockIdx.x * 128;
    int col0 = blockIdx.y * 128;
    int tx = t & 15, ty = t >> 4;
    int arow = t >> 1, acol = (t & 1) * 4;
    int brow = t >> 5, bcol = (t & 31) * 4;
    float acc[8][8];
    #pragma unroll
    for (int i = 0; i < 8; i++)
        #pragma unroll
        for (int j = 0; j < 8; j++) acc[i][j] = 0.f;

    for (int kt = 0; kt < K; kt += 8) {
        float4 a4 = make_float4(0.f, 0.f, 0.f, 0.f);
        int gr = row0 + arow;
        if (gr < M) a4 = *reinterpret_cast<const float4*>(&A[(size_t)gr * K + kt + acol]);
        As[acol + 0][arow] = a4.x;
        As[acol + 1][arow] = a4.y;
        As[acol + 2][arow] = a4.z;
        As[acol + 3][arow] = a4.w;
        float4 b4 = *reinterpret_cast<const float4*>(&B[(size_t)(kt + brow) * N + col0 + bcol]);
        *reinterpret_cast<float4*>(&Bs[brow][bcol]) = b4;
        __syncthreads();
        #pragma unroll
        for (int k = 0; k < 8; k++) {
            float ra[8], rb[8];
            #pragma unroll
            for (int i = 0; i < 8; i++) ra[i] = As[k][ty * 8 + i];
            #pragma unroll
            for (int j = 0; j < 8; j++) rb[j] = Bs[k][tx * 8 + j];
            #pragma unroll
            for (int i = 0; i < 8; i++)
                #pragma unroll
                for (int j = 0; j < 8; j++) acc[i][j] = fmaf(ra[i], rb[j], acc[i][j]);
        }
        __syncthreads();
    }
    #pragma unroll
    for (int i = 0; i < 8; i++) {
        int gr = row0 + ty * 8 + i;
        if (gr >= M) continue;
        #pragma unroll
        for (int j = 0; j < 8; j += 4) {
            int gc = col0 + tx * 8 + j;
            float4 o;
            o.x = fmaxf(acc[i][j + 0] + bias[gc + 0], 0.f);
            o.y = fmaxf(acc[i][j + 1] + bias[gc + 1], 0.f);
            o.z = fmaxf(acc[i][j + 2] + bias[gc + 2], 0.f);
            o.w = fmaxf(acc[i][j + 3] + bias[gc + 3], 0.f);
            *reinterpret_cast<float4*>(&C[(size_t)gr * N + gc]) = o;
        }
    }
}

// ---------------- attention logits + global max ----------------
__global__ void k_logits(const float* __restrict__ h2, const float* __restrict__ Wa,
                         const float* __restrict__ ba) {
    int node = (blockIdx.x * blockDim.x + threadIdx.x) >> 5;
    if (node >= N_NODES) return;
    int lane = threadIdx.x & 31;
    const float4* h = reinterpret_cast<const float4*>(h2) + (size_t)node * 64;
    const float4* w = reinterpret_cast<const float4*>(Wa);
    float4 a = h[lane], b = w[lane];
    float sum = a.x * b.x + a.y * b.y + a.z * b.z + a.w * b.w;
    a = h[lane + 32]; b = w[lane + 32];
    sum += a.x * b.x + a.y * b.y + a.z * b.z + a.w * b.w;
    #pragma unroll
    for (int off = 16; off; off >>= 1) sum += __shfl_xor_sync(0xffffffffu, sum, off);
    if (lane == 0) {
        float logit = sum + ba[0];
        g_logits[node] = logit;
        unsigned u = __float_as_uint(logit);
        u = (u & 0x80000000u) ? ~u : (u | 0x80000000u);  // order-preserving encode
        atomicMax(&g_max_enc, u);
    }
}

// ---------------- attention-weighted pooling (unnormalized) ----------------
__global__ void k_pool(const float* __restrict__ h2) {
    int f = threadIdx.x;  // 256 threads = 256 features
    unsigned u = g_max_enc;
    float m = (u & 0x80000000u) ? __uint_as_float(u & 0x7FFFFFFFu) : __uint_as_float(~u);
    float acc = 0.f, ws = 0.f;
    for (int r = blockIdx.x; r < N_NODES; r += gridDim.x) {
        float wgt = expf(g_logits[r] - m);
        acc = fmaf(h2[(size_t)r * OUT_DIM + f], wgt, acc);
        ws += wgt;
    }
    atomicAdd(&g_gacc[f], acc);
    if (f == 0) atomicAdd(&g_wsum, ws);
}

__global__ void k_finish(float* __restrict__ out_tail) {
    int f = threadIdx.x;
    if (f < OUT_DIM) out_tail[f] = g_gacc[f] / g_wsum;
}

// ---------------- launch ----------------
extern "C" void kernel_launch(void* const* d_in, const int* in_sizes, int n_in,
                              void* d_out, int out_size) {
    const float* x  = (const float*)d_in[0];
    const void*  ei = d_in[1];
    const float* W1 = (const float*)d_in[2];
    const float* b1 = (const float*)d_in[3];
    const float* W2 = (const float*)d_in[4];
    const float* b2 = (const float*)d_in[5];
    const float* Wa = (const float*)d_in[6];
    const float* ba = (const float*)d_in[7];
    float* out = (float*)d_out;

    float *bufA, *bufB;
    cudaGetSymbolAddress((void**)&bufA, g_bufA);
    cudaGetSymbolAddress((void**)&bufB, g_bufB);

    k_init<<<196, 256>>>();
    k_detect<<<1, 32>>>((const int*)ei);
    k_count<<<(N_EDGES + 255) / 256, 256>>>(ei);
    k_dinv<<<(N_NODES + 255) / 256, 256>>>();
    k_scan<<<1, 1024>>>();
    k_fill<<<(N_EDGES + 255) / 256, 256>>>(ei);

    // layer 1: h1 = relu(Agg(x) @ W1 + b1)
    k_agg<<<(N_NODES * 32 + 255) / 256, 256>>>(x, bufA);
    {
        dim3 grid((N_NODES + 127) / 128, F_DIM / 128);
        k_gemm_bias_relu<<<grid, 256>>>(bufA, W1, b1, bufB, N_NODES, F_DIM);
    }
    // layer 2: h2 = relu(Agg(h1) @ W2 + b2) -> d_out node section
    k_agg<<<(N_NODES * 32 + 255) / 256, 256>>>(bufB, bufA);
    {
        dim3 grid((N_NODES + 127) / 128, OUT_DIM / 128);
        k_gemm_bias_relu<<<grid, 256>>>(bufA, W2, b2, out, N_NODES, OUT_DIM);
    }
    // attention pooling
    k_logits<<<(N_NODES * 32 + 255) / 256, 256>>>(out, Wa, ba);
    k_pool<<<592, 256>>>(out);
    k_finish<<<1, 256>>>(out + (size_t)N_NODES * OUT_DIM);
}

// round 6
// speedup vs baseline: 1.1891x; 1.1891x over previous
#include <cuda_runtime.h>
#include <math.h>

#define N_NODES 50000
#define N_EDGES 800000
#define F_DIM   128
#define OUT_DIM 256
#define NBLK    196   // ceil(50000/256)

// ---------------- device scratch (no allocations allowed) ----------------
__device__ float    g_bufA[(size_t)N_NODES * F_DIM];
__device__ float    g_bufB[(size_t)N_NODES * F_DIM];
__device__ int      g_cnt[N_NODES];
__device__ int      g_rowptr[N_NODES + 1];
__device__ int      g_cursor[N_NODES];
__device__ int      g_col[N_EDGES];
__device__ float    g_dinv[N_NODES];
__device__ float    g_logits[N_NODES];   // raw logits, then exp weights
__device__ int      g_part[NBLK];
__device__ unsigned g_max_enc;
__device__ float    g_wsum;
__device__ float    g_gacc[OUT_DIM];
__device__ int      g_is64;

#define FMA2(c, a, b) asm("fma.rn.f32x2 %0, %1, %2, %0;" : "+l"(c) : "l"(a), "l"(b))

// ---------------- helpers ----------------
__device__ __forceinline__ int edge_src(const void* ei, int e) {
    return g_is64 ? (int)((const long long*)ei)[e] : ((const int*)ei)[e];
}
__device__ __forceinline__ int edge_dst(const void* ei, int e) {
    return g_is64 ? (int)((const long long*)ei)[(size_t)N_EDGES + e]
                  : ((const int*)ei)[(size_t)N_EDGES + e];
}

// ---------------- init + dtype detect ----------------
__global__ void k_init(const int* ei32) {
    int i = blockIdx.x * blockDim.x + threadIdx.x;
    int stride = gridDim.x * blockDim.x;
    for (int j = i; j < N_NODES; j += stride) {
        g_cnt[j] = 0; g_cursor[j] = 0; g_logits[j] = 0.f;
    }
    if (i < OUT_DIM) g_gacc[i] = 0.f;
    if (i == 0) {
        g_wsum = 0.f; g_max_enc = 0u; g_rowptr[N_NODES] = N_EDGES;
        int ornz = 0;
        #pragma unroll 8
        for (int k = 0; k < 256; k++) ornz |= ei32[2 * k + 1];
        g_is64 = (ornz == 0) ? 1 : 0;
    }
}

// ---------------- degree histogram ----------------
__global__ void k_count(const void* __restrict__ ei) {
    int e = blockIdx.x * blockDim.x + threadIdx.x;
    if (e >= N_EDGES) return;
    atomicAdd(&g_cnt[edge_dst(ei, e)], 1);
}

// ---------------- multi-block exclusive scan (3 kernels) + dinv ----------------
__global__ void k_scanA() {           // 196 blocks x 256: block sums + dinv
    __shared__ int sh[256];
    int t = threadIdx.x;
    int i = blockIdx.x * 256 + t;
    int v = (i < N_NODES) ? g_cnt[i] : 0;
    if (i < N_NODES) g_dinv[i] = rsqrtf((float)(v + 1));  // +1 self-loop
    sh[t] = v; __syncthreads();
    #pragma unroll
    for (int off = 128; off; off >>= 1) {
        if (t < off) sh[t] += sh[t + off];
        __syncthreads();
    }
    if (t == 0) g_part[blockIdx.x] = sh[0];
}

__global__ void k_scanB() {           // 1 block x 256: exclusive scan of partials
    __shared__ int sh[256];
    int t = threadIdx.x;
    int v = (t < NBLK) ? g_part[t] : 0;
    sh[t] = v; __syncthreads();
    #pragma unroll
    for (int off = 1; off < 256; off <<= 1) {
        int u = (t >= off) ? sh[t - off] : 0;
        __syncthreads();
        sh[t] += u;
        __syncthreads();
    }
    if (t < NBLK) g_part[t] = sh[t] - v;
}

__global__ void k_scanC() {           // 196 blocks x 256: final rowptr
    __shared__ int sh[256];
    int t = threadIdx.x;
    int i = blockIdx.x * 256 + t;
    int v = (i < N_NODES) ? g_cnt[i] : 0;
    sh[t] = v; __syncthreads();
    #pragma unroll
    for (int off = 1; off < 256; off <<= 1) {
        int u = (t >= off) ? sh[t - off] : 0;
        __syncthreads();
        sh[t] += u;
        __syncthreads();
    }
    if (i < N_NODES) g_rowptr[i] = g_part[blockIdx.x] + sh[t] - v;
}

__global__ void k_fill(const void* __restrict__ ei) {
    int e = blockIdx.x * blockDim.x + threadIdx.x;
    if (e >= N_EDGES) return;
    int s = edge_src(ei, e);
    int d = edge_dst(ei, e);
    int pos = g_rowptr[d] + atomicAdd(&g_cursor[d], 1);
    g_col[pos] = s;
}

// ---------------- GCN aggregation: one warp per node, unroll-4 for MLP ----------------
__global__ void k_agg(const float* __restrict__ in, float* __restrict__ out) {
    int node = (blockIdx.x * blockDim.x + threadIdx.x) >> 5;
    if (node >= N_NODES) return;
    int lane = threadIdx.x & 31;
    const float4* inv = reinterpret_cast<const float4*>(in);
    float di = g_dinv[node];
    float4 v = inv[(size_t)node * 32 + lane];
    float sw = di * di;
    float4 acc = make_float4(v.x * sw, v.y * sw, v.z * sw, v.w * sw);
    int p = g_rowptr[node], end = g_rowptr[node + 1];
    for (; p + 4 <= end; p += 4) {
        int s0 = g_col[p], s1 = g_col[p + 1], s2 = g_col[p + 2], s3 = g_col[p + 3];
        float4 u0 = inv[(size_t)s0 * 32 + lane];
        float4 u1 = inv[(size_t)s1 * 32 + lane];
        float4 u2 = inv[(size_t)s2 * 32 + lane];
        float4 u3 = inv[(size_t)s3 * 32 + lane];
        float w0 = g_dinv[s0] * di, w1 = g_dinv[s1] * di;
        float w2 = g_dinv[s2] * di, w3 = g_dinv[s3] * di;
        acc.x = fmaf(u0.x, w0, fmaf(u1.x, w1, fmaf(u2.x, w2, fmaf(u3.x, w3, acc.x))));
        acc.y = fmaf(u0.y, w0, fmaf(u1.y, w1, fmaf(u2.y, w2, fmaf(u3.y, w3, acc.y))));
        acc.z = fmaf(u0.z, w0, fmaf(u1.z, w1, fmaf(u2.z, w2, fmaf(u3.z, w3, acc.z))));
        acc.w = fmaf(u0.w, w0, fmaf(u1.w, w1, fmaf(u2.w, w2, fmaf(u3.w, w3, acc.w))));
    }
    for (; p < end; ++p) {
        int s = g_col[p];
        float w = g_dinv[s] * di;
        float4 u = inv[(size_t)s * 32 + lane];
        acc.x = fmaf(u.x, w, acc.x);
        acc.y = fmaf(u.y, w, acc.y);
        acc.z = fmaf(u.z, w, acc.z);
        acc.w = fmaf(u.w, w, acc.w);
    }
    reinterpret_cast<float4*>(out)[(size_t)node * 32 + lane] = acc;
}

// ---------------- SGEMM 128x128, K=128, FFMA2 (packed f32x2), bias+relu,
//                  optional fused attention-logit partials (Wa != nullptr) -------------
__global__ __launch_bounds__(256, 2) void k_gemm_bias_relu(
    const float* __restrict__ A, const float* __restrict__ B,
    const float* __restrict__ bias, float* __restrict__ C, int M, int N,
    const float* __restrict__ Wa) {
    const int K = 128;
    __shared__ __align__(16) float As2[8][256];  // duplicated: As2[k][2r]=As2[k][2r+1]=A[r][k]
    __shared__ __align__(16) float Bs[8][128];
    int t = threadIdx.x;
    int row0 = blockIdx.x * 128;
    int col0 = blockIdx.y * 128;
    int tx = t & 15, ty = t >> 4;
    int arow = t >> 1, acol = (t & 1) * 4;
    int brow = t >> 5, bcol = (t & 31) * 4;

    unsigned long long acc[8][4];
    #pragma unroll
    for (int i = 0; i < 8; i++)
        #pragma unroll
        for (int j = 0; j < 4; j++) acc[i][j] = 0ull;

    for (int kt = 0; kt < K; kt += 8) {
        float4 a4 = make_float4(0.f, 0.f, 0.f, 0.f);
        int gr = row0 + arow;
        if (gr < M) a4 = *reinterpret_cast<const float4*>(&A[(size_t)gr * K + kt + acol]);
        *reinterpret_cast<float2*>(&As2[acol + 0][2 * arow]) = make_float2(a4.x, a4.x);
        *reinterpret_cast<float2*>(&As2[acol + 1][2 * arow]) = make_float2(a4.y, a4.y);
        *reinterpret_cast<float2*>(&As2[acol + 2][2 * arow]) = make_float2(a4.z, a4.z);
        *reinterpret_cast<float2*>(&As2[acol + 3][2 * arow]) = make_float2(a4.w, a4.w);
        float4 b4 = *reinterpret_cast<const float4*>(&B[(size_t)(kt + brow) * N + col0 + bcol]);
        *reinterpret_cast<float4*>(&Bs[brow][bcol]) = b4;
        __syncthreads();
        #pragma unroll
        for (int k = 0; k < 8; k++) {
            ulonglong2 a01 = *reinterpret_cast<ulonglong2*>(&As2[k][ty * 16 + 0]);
            ulonglong2 a23 = *reinterpret_cast<ulonglong2*>(&As2[k][ty * 16 + 4]);
            ulonglong2 a45 = *reinterpret_cast<ulonglong2*>(&As2[k][ty * 16 + 8]);
            ulonglong2 a67 = *reinterpret_cast<ulonglong2*>(&As2[k][ty * 16 + 12]);
            ulonglong2 b03 = *reinterpret_cast<ulonglong2*>(&Bs[k][tx * 8]);
            ulonglong2 b47 = *reinterpret_cast<ulonglong2*>(&Bs[k][tx * 8 + 4]);
            unsigned long long aD[8] = {a01.x, a01.y, a23.x, a23.y, a45.x, a45.y, a67.x, a67.y};
            unsigned long long bP[4] = {b03.x, b03.y, b47.x, b47.y};
            #pragma unroll
            for (int i = 0; i < 8; i++)
                #pragma unroll
                for (int j = 0; j < 4; j++) FMA2(acc[i][j], aD[i], bP[j]);
        }
        __syncthreads();
    }

    float wa[8];
    if (Wa) {
        #pragma unroll
        for (int j = 0; j < 8; j++) wa[j] = Wa[col0 + tx * 8 + j];
    }
    float lpart[8];
    #pragma unroll
    for (int i = 0; i < 8; i++) {
        int gr = row0 + ty * 8 + i;
        float o[8];
        #pragma unroll
        for (int jp = 0; jp < 4; jp++) {
            float lo, hi;
            asm("mov.b64 {%0, %1}, %2;" : "=f"(lo), "=f"(hi) : "l"(acc[i][jp]));
            o[2 * jp]     = fmaxf(lo + bias[col0 + tx * 8 + 2 * jp], 0.f);
            o[2 * jp + 1] = fmaxf(hi + bias[col0 + tx * 8 + 2 * jp + 1], 0.f);
        }
        float lp = 0.f;
        if (gr < M) {
            int gc = col0 + tx * 8;
            *reinterpret_cast<float4*>(&C[(size_t)gr * N + gc]) =
                make_float4(o[0], o[1], o[2], o[3]);
            *reinterpret_cast<float4*>(&C[(size_t)gr * N + gc + 4]) =
                make_float4(o[4], o[5], o[6], o[7]);
            if (Wa) {
                #pragma unroll
                for (int j = 0; j < 8; j++) lp = fmaf(o[j], wa[j], lp);
            }
        }
        lpart[i] = lp;
    }
    if (Wa) {
        #pragma unroll
        for (int i = 0; i < 8; i++) {
            #pragma unroll
            for (int off = 1; off < 16; off <<= 1)
                lpart[i] += __shfl_xor_sync(0xffffffffu, lpart[i], off);
        }
        if (tx == 0) {
            #pragma unroll
            for (int i = 0; i < 8; i++) {
                int gr = row0 + ty * 8 + i;
                if (gr < M) atomicAdd(&g_logits[gr], lpart[i]);
            }
        }
    }
}

// ---------------- softmax: global max (order-preserving encode) ----------------
__global__ void k_maxenc() {
    int i = blockIdx.x * blockDim.x + threadIdx.x;
    unsigned u = 0u;
    if (i < N_NODES) {
        unsigned b = __float_as_uint(g_logits[i]);
        u = (b & 0x80000000u) ? ~b : (b | 0x80000000u);
    }
    #pragma unroll
    for (int off = 16; off; off >>= 1) u = max(u, __shfl_xor_sync(0xffffffffu, u, off));
    if ((threadIdx.x & 31) == 0) atomicMax(&g_max_enc, u);
}

// ---------------- exp weights (ONE expf per node) + weight sum ----------------
__global__ void k_expw() {
    int i = blockIdx.x * blockDim.x + threadIdx.x;
    unsigned u = g_max_enc;
    float m = (u & 0x80000000u) ? __uint_as_float(u & 0x7FFFFFFFu) : __uint_as_float(~u);
    float w = 0.f;
    if (i < N_NODES) {
        w = expf(g_logits[i] - m);
        g_logits[i] = w;
    }
    #pragma unroll
    for (int off = 16; off; off >>= 1) w += __shfl_xor_sync(0xffffffffu, w, off);
    if ((threadIdx.x & 31) == 0) atomicAdd(&g_wsum, w);
}

// ---------------- weighted pooling: pure streaming now ----------------
__global__ void k_pool(const float* __restrict__ h2) {
    int f = threadIdx.x;  // 256 threads = 256 features
    float acc = 0.f;
    for (int r = blockIdx.x; r < N_NODES; r += gridDim.x)
        acc = fmaf(h2[(size_t)r * OUT_DIM + f], g_logits[r], acc);
    atomicAdd(&g_gacc[f], acc);
}

__global__ void k_finish(float* __restrict__ out_tail) {
    int f = threadIdx.x;
    if (f < OUT_DIM) out_tail[f] = g_gacc[f] / g_wsum;
}

// ---------------- launch ----------------
extern "C" void kernel_launch(void* const* d_in, const int* in_sizes, int n_in,
                              void* d_out, int out_size) {
    const float* x  = (const float*)d_in[0];
    const void*  ei = d_in[1];
    const float* W1 = (const float*)d_in[2];
    const float* b1 = (const float*)d_in[3];
    const float* W2 = (const float*)d_in[4];
    const float* b2 = (const float*)d_in[5];
    const float* Wa = (const float*)d_in[6];
    float* out = (float*)d_out;

    float *bufA, *bufB;
    cudaGetSymbolAddress((void**)&bufA, g_bufA);
    cudaGetSymbolAddress((void**)&bufB, g_bufB);

    // CSR build
    k_init<<<NBLK, 256>>>((const int*)ei);
    k_count<<<(N_EDGES + 255) / 256, 256>>>(ei);
    k_scanA<<<NBLK, 256>>>();
    k_scanB<<<1, 256>>>();
    k_scanC<<<NBLK, 256>>>();
    k_fill<<<(N_EDGES + 255) / 256, 256>>>(ei);

    // layer 1: h1 = relu(Agg(x) @ W1 + b1)
    k_agg<<<(N_NODES * 32 + 255) / 256, 256>>>(x, bufA);
    {
        dim3 grid((N_NODES + 127) / 128, F_DIM / 128);
        k_gemm_bias_relu<<<grid, 256>>>(bufA, W1, b1, bufB, N_NODES, F_DIM, nullptr);
    }
    // layer 2: h2 = relu(Agg(h1) @ W2 + b2), logits fused into epilogue
    k_agg<<<(N_NODES * 32 + 255) / 256, 256>>>(bufB, bufA);
    {
        dim3 grid((N_NODES + 127) / 128, OUT_DIM / 128);
        k_gemm_bias_relu<<<grid, 256>>>(bufA, W2, b2, out, N_NODES, OUT_DIM, Wa);
    }
    // softmax-weighted pooling
    k_maxenc<<<NBLK, 256>>>();
    k_expw<<<NBLK, 256>>>();
    k_pool<<<592, 256>>>(out);
    k_finish<<<1, 256>>>(out + (size_t)N_NODES * OUT_DIM);
}

// round 7
// speedup vs baseline: 1.3839x; 1.1639x over previous
#include <cuda_runtime.h>
#include <math.h>

#define N_NODES 50000
#define N_EDGES 800000
#define F_DIM   128
#define OUT_DIM 256
#define NBLK    196   // ceil(50000/256)

// ---------------- device scratch (no allocations allowed) ----------------
__device__ float    g_bufA[(size_t)N_NODES * F_DIM];
__device__ float    g_bufB[(size_t)N_NODES * F_DIM];
__device__ int      g_cnt[N_NODES];
__device__ int      g_rowptr[N_NODES + 1];
__device__ int      g_cursor[N_NODES];
__device__ int      g_col[N_EDGES];
__device__ float    g_dinv[N_NODES];
__device__ float    g_logits[N_NODES];   // raw logits, then exp weights
__device__ int      g_part[NBLK];
__device__ unsigned g_max_enc;
__device__ float    g_wsum;
__device__ float    g_gacc[OUT_DIM];
__device__ int      g_is64;

#define FMA2(c, a, b) asm("fma.rn.f32x2 %0, %1, %2, %0;" : "+l"(c) : "l"(a), "l"(b))

// ---------------- helpers ----------------
__device__ __forceinline__ int edge_src(const void* ei, int e) {
    return g_is64 ? (int)((const long long*)ei)[e] : ((const int*)ei)[e];
}
__device__ __forceinline__ int edge_dst(const void* ei, int e) {
    return g_is64 ? (int)((const long long*)ei)[(size_t)N_EDGES + e]
                  : ((const int*)ei)[(size_t)N_EDGES + e];
}

// ---------------- init (1 block): flags + gacc + dtype detect ----------------
__global__ void k_init(const int* __restrict__ ei32) {
    int t = threadIdx.x;
    g_gacc[t] = 0.f;   // blockDim == OUT_DIM == 256
    if (t == 0) {
        g_wsum = 0.f; g_max_enc = 0u; g_rowptr[N_NODES] = N_EDGES;
        int ornz = 0;
        #pragma unroll 8
        for (int k = 0; k < 256; k++) ornz |= ei32[2 * k + 1];
        g_is64 = (ornz == 0) ? 1 : 0;
    }
}

__global__ void k_zero_cnt() {
    int i = blockIdx.x * blockDim.x + threadIdx.x;
    if (i < N_NODES) g_cnt[i] = 0;
}

// ---------------- degree histogram ----------------
__global__ void k_count(const void* __restrict__ ei) {
    int e = blockIdx.x * blockDim.x + threadIdx.x;
    if (e >= N_EDGES) return;
    atomicAdd(&g_cnt[edge_dst(ei, e)], 1);
}

// ---------------- scanA: block sums + dinv + zero cursor/logits ----------------
__global__ void k_scanA() {
    __shared__ int sh[256];
    int t = threadIdx.x;
    int i = blockIdx.x * 256 + t;
    int v = (i < N_NODES) ? g_cnt[i] : 0;
    if (i < N_NODES) {
        g_dinv[i] = rsqrtf((float)(v + 1));  // +1 self-loop
        g_cursor[i] = 0;
        g_logits[i] = 0.f;
    }
    sh[t] = v; __syncthreads();
    #pragma unroll
    for (int off = 128; off; off >>= 1) {
        if (t < off) sh[t] += sh[t + off];
        __syncthreads();
    }
    if (t == 0) g_part[blockIdx.x] = sh[0];
}

// ---------------- scanC: redundant partial-scan per block + final rowptr -------
__global__ void k_scanC() {
    __shared__ int shp[256];
    __shared__ int sh[256];
    __shared__ int base;
    int t = threadIdx.x;
    int pv = (t < NBLK) ? g_part[t] : 0;
    shp[t] = pv; __syncthreads();
    #pragma unroll
    for (int off = 1; off < 256; off <<= 1) {
        int u = (t >= off) ? shp[t - off] : 0;
        __syncthreads();
        shp[t] += u;
        __syncthreads();
    }
    if (t == (int)blockIdx.x) base = shp[t] - pv;  // exclusive prefix for this block
    int i = blockIdx.x * 256 + t;
    int v = (i < N_NODES) ? g_cnt[i] : 0;
    sh[t] = v; __syncthreads();
    #pragma unroll
    for (int off = 1; off < 256; off <<= 1) {
        int u = (t >= off) ? sh[t - off] : 0;
        __syncthreads();
        sh[t] += u;
        __syncthreads();
    }
    if (i < N_NODES) g_rowptr[i] = base + sh[t] - v;
}

__global__ void k_fill(const void* __restrict__ ei) {
    int e = blockIdx.x * blockDim.x + threadIdx.x;
    if (e >= N_EDGES) return;
    int s = edge_src(ei, e);
    int d = edge_dst(ei, e);
    int pos = g_rowptr[d] + atomicAdd(&g_cursor[d], 1);
    g_col[pos] = s;
}

// ---------------- GCN aggregation: one warp per node, unroll-4, optional bias+relu
__global__ void k_agg(const float* __restrict__ in, float* __restrict__ out,
                      const float* __restrict__ bias) {
    int node = (blockIdx.x * blockDim.x + threadIdx.x) >> 5;
    if (node >= N_NODES) return;
    int lane = threadIdx.x & 31;
    const float4* inv = reinterpret_cast<const float4*>(in);
    float di = g_dinv[node];
    float4 v = inv[(size_t)node * 32 + lane];
    float sw = di * di;
    float4 acc = make_float4(v.x * sw, v.y * sw, v.z * sw, v.w * sw);
    int p = g_rowptr[node], end = g_rowptr[node + 1];
    for (; p + 4 <= end; p += 4) {
        int s0 = g_col[p], s1 = g_col[p + 1], s2 = g_col[p + 2], s3 = g_col[p + 3];
        float4 u0 = inv[(size_t)s0 * 32 + lane];
        float4 u1 = inv[(size_t)s1 * 32 + lane];
        float4 u2 = inv[(size_t)s2 * 32 + lane];
        float4 u3 = inv[(size_t)s3 * 32 + lane];
        float w0 = g_dinv[s0] * di, w1 = g_dinv[s1] * di;
        float w2 = g_dinv[s2] * di, w3 = g_dinv[s3] * di;
        acc.x = fmaf(u0.x, w0, fmaf(u1.x, w1, fmaf(u2.x, w2, fmaf(u3.x, w3, acc.x))));
        acc.y = fmaf(u0.y, w0, fmaf(u1.y, w1, fmaf(u2.y, w2, fmaf(u3.y, w3, acc.y))));
        acc.z = fmaf(u0.z, w0, fmaf(u1.z, w1, fmaf(u2.z, w2, fmaf(u3.z, w3, acc.z))));
        acc.w = fmaf(u0.w, w0, fmaf(u1.w, w1, fmaf(u2.w, w2, fmaf(u3.w, w3, acc.w))));
    }
    for (; p < end; ++p) {
        int s = g_col[p];
        float w = g_dinv[s] * di;
        float4 u = inv[(size_t)s * 32 + lane];
        acc.x = fmaf(u.x, w, acc.x);
        acc.y = fmaf(u.y, w, acc.y);
        acc.z = fmaf(u.z, w, acc.z);
        acc.w = fmaf(u.w, w, acc.w);
    }
    if (bias) {
        float4 bv = reinterpret_cast<const float4*>(bias)[lane];
        acc.x = fmaxf(acc.x + bv.x, 0.f);
        acc.y = fmaxf(acc.y + bv.y, 0.f);
        acc.z = fmaxf(acc.z + bv.z, 0.f);
        acc.w = fmaxf(acc.w + bv.w, 0.f);
    }
    reinterpret_cast<float4*>(out)[(size_t)node * 32 + lane] = acc;
}

// ---------------- SGEMM 128x128, K=128, FFMA2, double-buffered smem,
//                  optional bias+relu epilogue and fused attention-logit partials
__global__ __launch_bounds__(256, 2) void k_gemm(
    const float* __restrict__ A, const float* __restrict__ B,
    const float* __restrict__ bias, float* __restrict__ C, int M, int N,
    const float* __restrict__ Wa) {
    const int K = 128;
    __shared__ __align__(16) float As2[2][8][256];  // duplicated A: (a,a) pairs
    __shared__ __align__(16) float Bs[2][8][128];
    int t = threadIdx.x;
    int row0 = blockIdx.x * 128;
    int col0 = blockIdx.y * 128;
    int tx = t & 15, ty = t >> 4;
    int arow = t >> 1, acol = (t & 1) * 4;
    int brow = t >> 5, bcol = (t & 31) * 4;
    int grA = row0 + arow;
    const float* Aptr = A + (size_t)grA * K + acol;
    const float* Bptr = B + (size_t)brow * N + col0 + bcol;

    float4 a4 = (grA < M) ? *reinterpret_cast<const float4*>(Aptr)
                          : make_float4(0.f, 0.f, 0.f, 0.f);
    float4 b4 = *reinterpret_cast<const float4*>(Bptr);

    unsigned long long acc[8][4];
    #pragma unroll
    for (int i = 0; i < 8; i++)
        #pragma unroll
        for (int j = 0; j < 4; j++) acc[i][j] = 0ull;

    int buf = 0;
    for (int kt = 0; kt < K; kt += 8) {
        // store prefetched tile into smem[buf]
        *reinterpret_cast<float2*>(&As2[buf][acol + 0][2 * arow]) = make_float2(a4.x, a4.x);
        *reinterpret_cast<float2*>(&As2[buf][acol + 1][2 * arow]) = make_float2(a4.y, a4.y);
        *reinterpret_cast<float2*>(&As2[buf][acol + 2][2 * arow]) = make_float2(a4.z, a4.z);
        *reinterpret_cast<float2*>(&As2[buf][acol + 3][2 * arow]) = make_float2(a4.w, a4.w);
        *reinterpret_cast<float4*>(&Bs[buf][brow][bcol]) = b4;
        __syncthreads();
        // prefetch next tile (global -> regs) while computing current
        if (kt + 8 < K) {
            a4 = (grA < M) ? *reinterpret_cast<const float4*>(Aptr + kt + 8)
                           : make_float4(0.f, 0.f, 0.f, 0.f);
            b4 = *reinterpret_cast<const float4*>(Bptr + (size_t)(kt + 8) * N);
        }
        #pragma unroll
        for (int k = 0; k < 8; k++) {
            ulonglong2 a01 = *reinterpret_cast<ulonglong2*>(&As2[buf][k][ty * 16 + 0]);
            ulonglong2 a23 = *reinterpret_cast<ulonglong2*>(&As2[buf][k][ty * 16 + 4]);
            ulonglong2 a45 = *reinterpret_cast<ulonglong2*>(&As2[buf][k][ty * 16 + 8]);
            ulonglong2 a67 = *reinterpret_cast<ulonglong2*>(&As2[buf][k][ty * 16 + 12]);
            ulonglong2 b03 = *reinterpret_cast<ulonglong2*>(&Bs[buf][k][tx * 8]);
            ulonglong2 b47 = *reinterpret_cast<ulonglong2*>(&Bs[buf][k][tx * 8 + 4]);
            unsigned long long aD[8] = {a01.x, a01.y, a23.x, a23.y, a45.x, a45.y, a67.x, a67.y};
            unsigned long long bP[4] = {b03.x, b03.y, b47.x, b47.y};
            #pragma unroll
            for (int i = 0; i < 8; i++)
                #pragma unroll
                for (int j = 0; j < 4; j++) FMA2(acc[i][j], aD[i], bP[j]);
        }
        buf ^= 1;
    }

    float wa[8];
    if (Wa) {
        #pragma unroll
        for (int j = 0; j < 8; j++) wa[j] = Wa[col0 + tx * 8 + j];
    }
    float lpart[8];
    #pragma unroll
    for (int i = 0; i < 8; i++) {
        int gr = row0 + ty * 8 + i;
        float o[8];
        #pragma unroll
        for (int jp = 0; jp < 4; jp++) {
            float lo, hi;
            asm("mov.b64 {%0, %1}, %2;" : "=f"(lo), "=f"(hi) : "l"(acc[i][jp]));
            if (bias) {
                lo = fmaxf(lo + bias[col0 + tx * 8 + 2 * jp], 0.f);
                hi = fmaxf(hi + bias[col0 + tx * 8 + 2 * jp + 1], 0.f);
            }
            o[2 * jp] = lo; o[2 * jp + 1] = hi;
        }
        float lp = 0.f;
        if (gr < M) {
            int gc = col0 + tx * 8;
            *reinterpret_cast<float4*>(&C[(size_t)gr * N + gc]) =
                make_float4(o[0], o[1], o[2], o[3]);
            *reinterpret_cast<float4*>(&C[(size_t)gr * N + gc + 4]) =
                make_float4(o[4], o[5], o[6], o[7]);
            if (Wa) {
                #pragma unroll
                for (int j = 0; j < 8; j++) lp = fmaf(o[j], wa[j], lp);
            }
        }
        lpart[i] = lp;
    }
    if (Wa) {
        #pragma unroll
        for (int i = 0; i < 8; i++) {
            #pragma unroll
            for (int off = 1; off < 16; off <<= 1)
                lpart[i] += __shfl_xor_sync(0xffffffffu, lpart[i], off);
        }
        if (tx == 0) {
            #pragma unroll
            for (int i = 0; i < 8; i++) {
                int gr = row0 + ty * 8 + i;
                if (gr < M) atomicAdd(&g_logits[gr], lpart[i]);
            }
        }
    }
}

// ---------------- softmax: global max (order-preserving encode) ----------------
__global__ void k_maxenc() {
    int i = blockIdx.x * blockDim.x + threadIdx.x;
    unsigned u = 0u;
    if (i < N_NODES) {
        unsigned b = __float_as_uint(g_logits[i]);
        u = (b & 0x80000000u) ? ~b : (b | 0x80000000u);
    }
    #pragma unroll
    for (int off = 16; off; off >>= 1) u = max(u, __shfl_xor_sync(0xffffffffu, u, off));
    if ((threadIdx.x & 31) == 0) atomicMax(&g_max_enc, u);
}

// ---------------- exp weights (one expf per node) + weight sum ----------------
__global__ void k_expw() {
    int i = blockIdx.x * blockDim.x + threadIdx.x;
    unsigned u = g_max_enc;
    float m = (u & 0x80000000u) ? __uint_as_float(u & 0x7FFFFFFFu) : __uint_as_float(~u);
    float w = 0.f;
    if (i < N_NODES) {
        w = expf(g_logits[i] - m);
        g_logits[i] = w;
    }
    #pragma unroll
    for (int off = 16; off; off >>= 1) w += __shfl_xor_sync(0xffffffffu, w, off);
    if ((threadIdx.x & 31) == 0) atomicAdd(&g_wsum, w);
}

// ---------------- weighted pooling ----------------
__global__ void k_pool(const float* __restrict__ h2) {
    int f = threadIdx.x;  // 256 threads = 256 features
    float acc = 0.f;
    for (int r = blockIdx.x; r < N_NODES; r += gridDim.x)
        acc = fmaf(h2[(size_t)r * OUT_DIM + f], g_logits[r], acc);
    atomicAdd(&g_gacc[f], acc);
}

__global__ void k_finish(float* __restrict__ out_tail) {
    int f = threadIdx.x;
    if (f < OUT_DIM) out_tail[f] = g_gacc[f] / g_wsum;
}

// ---------------- launch ----------------
extern "C" void kernel_launch(void* const* d_in, const int* in_sizes, int n_in,
                              void* d_out, int out_size) {
    const float* x  = (const float*)d_in[0];
    const void*  ei = d_in[1];
    const float* W1 = (const float*)d_in[2];
    const float* b1 = (const float*)d_in[3];
    const float* W2 = (const float*)d_in[4];
    const float* b2 = (const float*)d_in[5];
    const float* Wa = (const float*)d_in[6];
    float* out = (float*)d_out;

    float *bufA, *bufB;
    cudaGetSymbolAddress((void**)&bufA, g_bufA);
    cudaGetSymbolAddress((void**)&bufB, g_bufB);

    // one-time resource creation (happens on the first, non-captured correctness
    // call; subsequent captured calls reuse — no allocation during capture)
    static cudaStream_t s2 = nullptr;
    static cudaEvent_t evFork = nullptr, evJoin = nullptr;
    if (!s2) {
        cudaStreamCreateWithFlags(&s2, cudaStreamNonBlocking);
        cudaEventCreateWithFlags(&evFork, cudaEventDisableTiming);
        cudaEventCreateWithFlags(&evJoin, cudaEventDisableTiming);
    }

    // fork: CSR build on s2, GEMM1 (x@W1, no graph dependency) on main stream
    cudaEventRecord(evFork, 0);
    cudaStreamWaitEvent(s2, evFork, 0);

    k_init<<<1, 256, 0, s2>>>((const int*)ei);
    k_zero_cnt<<<NBLK, 256, 0, s2>>>();
    k_count<<<(N_EDGES + 255) / 256, 256, 0, s2>>>(ei);
    k_scanA<<<NBLK, 256, 0, s2>>>();
    k_scanC<<<NBLK, 256, 0, s2>>>();
    k_fill<<<(N_EDGES + 255) / 256, 256, 0, s2>>>(ei);
    cudaEventRecord(evJoin, s2);

    {   // GEMM1 raw: bufB = x @ W1   (layer1 re-associated: relu(Agg(xW1)+b1))
        dim3 grid((N_NODES + 127) / 128, F_DIM / 128);
        k_gemm<<<grid, 256>>>(x, W1, nullptr, bufB, N_NODES, F_DIM, nullptr);
    }
    cudaStreamWaitEvent(0, evJoin, 0);

    // layer 1 aggregation with fused bias+relu: bufA = h1
    k_agg<<<(N_NODES * 32 + 255) / 256, 256>>>(bufB, bufA, b1);
    // layer 2: agg (raw) then GEMM with bias+relu+logits
    k_agg<<<(N_NODES * 32 + 255) / 256, 256>>>(bufA, bufB, nullptr);
    {
        dim3 grid((N_NODES + 127) / 128, OUT_DIM / 128);
        k_gemm<<<grid, 256>>>(bufB, W2, b2, out, N_NODES, OUT_DIM, Wa);
    }
    // softmax-weighted pooling
    k_maxenc<<<NBLK, 256>>>();
    k_expw<<<NBLK, 256>>>();
    k_pool<<<592, 256>>>(out);
    k_finish<<<1, 256>>>(out + (size_t)N_NODES * OUT_DIM);
}

// round 9
// speedup vs baseline: 2.0436x; 1.4766x over previous
#include <cuda_runtime.h>
#include <math.h>

#define N_NODES 50000
#define N_EDGES 800000
#define F_DIM   128
#define OUT_DIM 256
#define NBLK    196   // ceil(50000/256)

// ---------------- device scratch (no allocations allowed) ----------------
__device__ float    g_bufA[(size_t)N_NODES * F_DIM];
__device__ float    g_bufB[(size_t)N_NODES * F_DIM];
__device__ int      g_cnt[N_NODES];
__device__ int      g_rowptr[N_NODES + 1];
__device__ int      g_cursor[N_NODES];
__device__ int      g_col[N_EDGES];
__device__ float    g_dinv[N_NODES];
__device__ float    g_logits[N_NODES];   // raw logits, then exp weights
__device__ int      g_part[NBLK];
__device__ unsigned g_max_enc;
__device__ float    g_wsum;
__device__ float    g_gacc[OUT_DIM];
__device__ int      g_is64;

// ---------------- helpers ----------------
__device__ __forceinline__ int edge_src(const void* ei, int e) {
    return g_is64 ? (int)((const long long*)ei)[e] : ((const int*)ei)[e];
}
__device__ __forceinline__ int edge_dst(const void* ei, int e) {
    return g_is64 ? (int)((const long long*)ei)[(size_t)N_EDGES + e]
                  : ((const int*)ei)[(size_t)N_EDGES + e];
}
__device__ __forceinline__ unsigned f2tf(float f) {
    unsigned r;
    asm("cvt.rna.tf32.f32 %0, %1;" : "=r"(r) : "f"(f));
    return r;
}
__device__ __forceinline__ void mma_tf32(float& c0, float& c1, float& c2, float& c3,
                                         unsigned a0, unsigned a1, unsigned a2, unsigned a3,
                                         unsigned b0, unsigned b1) {
    asm volatile("mma.sync.aligned.m16n8k8.row.col.f32.tf32.tf32.f32 "
                 "{%0,%1,%2,%3}, {%4,%5,%6,%7}, {%8,%9}, {%0,%1,%2,%3};"
                 : "+f"(c0), "+f"(c1), "+f"(c2), "+f"(c3)
                 : "r"(a0), "r"(a1), "r"(a2), "r"(a3), "r"(b0), "r"(b1));
}

// ---------------- init: zero cnt + gacc/scalars + dtype detect ----------------
__global__ void k_init(const int* __restrict__ ei32) {
    int i = blockIdx.x * 256 + threadIdx.x;
    if (i < N_NODES) g_cnt[i] = 0;
    if (blockIdx.x == 0) {
        g_gacc[threadIdx.x] = 0.f;
        if (threadIdx.x == 0) {
            g_wsum = 0.f; g_max_enc = 0u; g_rowptr[N_NODES] = N_EDGES;
            int ornz = 0;
            #pragma unroll 8
            for (int k = 0; k < 256; k++) ornz |= ei32[2 * k + 1];
            g_is64 = (ornz == 0) ? 1 : 0;
        }
    }
}

// ---------------- degree histogram ----------------
__global__ void k_count(const void* __restrict__ ei) {
    int e = blockIdx.x * blockDim.x + threadIdx.x;
    if (e >= N_EDGES) return;
    atomicAdd(&g_cnt[edge_dst(ei, e)], 1);
}

// ---------------- scanA: block sums + dinv + zero cursor/logits ----------------
__global__ void k_scanA() {
    __shared__ int sh[256];
    int t = threadIdx.x;
    int i = blockIdx.x * 256 + t;
    int v = (i < N_NODES) ? g_cnt[i] : 0;
    if (i < N_NODES) {
        g_dinv[i] = rsqrtf((float)(v + 1));  // +1 self-loop
        g_cursor[i] = 0;
        g_logits[i] = 0.f;
    }
    sh[t] = v; __syncthreads();
    #pragma unroll
    for (int off = 128; off; off >>= 1) {
        if (t < off) sh[t] += sh[t + off];
        __syncthreads();
    }
    if (t == 0) g_part[blockIdx.x] = sh[0];
}

// ---------------- scanC: redundant partial-scan per block + final rowptr -------
__global__ void k_scanC() {
    __shared__ int shp[256];
    __shared__ int sh[256];
    __shared__ int base;
    int t = threadIdx.x;
    int pv = (t < NBLK) ? g_part[t] : 0;
    shp[t] = pv; __syncthreads();
    #pragma unroll
    for (int off = 1; off < 256; off <<= 1) {
        int u = (t >= off) ? shp[t - off] : 0;
        __syncthreads();
        shp[t] += u;
        __syncthreads();
    }
    if (t == (int)blockIdx.x) base = shp[t] - pv;
    int i = blockIdx.x * 256 + t;
    int v = (i < N_NODES) ? g_cnt[i] : 0;
    sh[t] = v; __syncthreads();
    #pragma unroll
    for (int off = 1; off < 256; off <<= 1) {
        int u = (t >= off) ? sh[t - off] : 0;
        __syncthreads();
        sh[t] += u;
        __syncthreads();
    }
    if (i < N_NODES) g_rowptr[i] = base + sh[t] - v;
}

__global__ void k_fill(const void* __restrict__ ei) {
    int e = blockIdx.x * blockDim.x + threadIdx.x;
    if (e >= N_EDGES) return;
    int s = edge_src(ei, e);
    int d = edge_dst(ei, e);
    int pos = g_rowptr[d] + atomicAdd(&g_cursor[d], 1);
    g_col[pos] = s;
}

// ---------------- GCN aggregation: one warp per node, unroll-4, optional bias+relu
__global__ void k_agg(const float* __restrict__ in, float* __restrict__ out,
                      const float* __restrict__ bias) {
    int node = (blockIdx.x * blockDim.x + threadIdx.x) >> 5;
    if (node >= N_NODES) return;
    int lane = threadIdx.x & 31;
    const float4* inv = reinterpret_cast<const float4*>(in);
    float di = g_dinv[node];
    float4 v = inv[(size_t)node * 32 + lane];
    float sw = di * di;
    float4 acc = make_float4(v.x * sw, v.y * sw, v.z * sw, v.w * sw);
    int p = g_rowptr[node], end = g_rowptr[node + 1];
    for (; p + 4 <= end; p += 4) {
        int s0 = g_col[p], s1 = g_col[p + 1], s2 = g_col[p + 2], s3 = g_col[p + 3];
        float4 u0 = inv[(size_t)s0 * 32 + lane];
        float4 u1 = inv[(size_t)s1 * 32 + lane];
        float4 u2 = inv[(size_t)s2 * 32 + lane];
        float4 u3 = inv[(size_t)s3 * 32 + lane];
        float w0 = g_dinv[s0] * di, w1 = g_dinv[s1] * di;
        float w2 = g_dinv[s2] * di, w3 = g_dinv[s3] * di;
        acc.x = fmaf(u0.x, w0, fmaf(u1.x, w1, fmaf(u2.x, w2, fmaf(u3.x, w3, acc.x))));
        acc.y = fmaf(u0.y, w0, fmaf(u1.y, w1, fmaf(u2.y, w2, fmaf(u3.y, w3, acc.y))));
        acc.z = fmaf(u0.z, w0, fmaf(u1.z, w1, fmaf(u2.z, w2, fmaf(u3.z, w3, acc.z))));
        acc.w = fmaf(u0.w, w0, fmaf(u1.w, w1, fmaf(u2.w, w2, fmaf(u3.w, w3, acc.w))));
    }
    for (; p < end; ++p) {
        int s = g_col[p];
        float w = g_dinv[s] * di;
        float4 u = inv[(size_t)s * 32 + lane];
        acc.x = fmaf(u.x, w, acc.x);
        acc.y = fmaf(u.y, w, acc.y);
        acc.z = fmaf(u.z, w, acc.z);
        acc.w = fmaf(u.w, w, acc.w);
    }
    if (bias) {
        float4 bv = reinterpret_cast<const float4*>(bias)[lane];
        acc.x = fmaxf(acc.x + bv.x, 0.f);
        acc.y = fmaxf(acc.y + bv.y, 0.f);
        acc.z = fmaxf(acc.z + bv.z, 0.f);
        acc.w = fmaxf(acc.w + bv.w, 0.f);
    }
    reinterpret_cast<float4*>(out)[(size_t)node * 32 + lane] = acc;
}

// ---------------- TF32 tensor-core GEMM: 128x128 tile, K=128, kchunk=16,
//                  double-buffered, optional bias+relu and fused Wa logits ------
#define AS_STRIDE 20
#define BS_STRIDE 136
__global__ __launch_bounds__(256, 2) void k_gemm(
    const float* __restrict__ A, const float* __restrict__ B,
    const float* __restrict__ bias, float* __restrict__ C, int M, int N,
    const float* __restrict__ Wa) {
    const int K = 128;
    __shared__ unsigned As[2][128 * AS_STRIDE];
    __shared__ unsigned Bs[2][16 * BS_STRIDE];

    int t = threadIdx.x;
    int lane = t & 31;
    int warp = t >> 5;
    int g = lane >> 2, tig = lane & 3;
    int row0 = blockIdx.x * 128;
    int col0 = blockIdx.y * 128;
    int warpM = warp & 3, warpN = warp >> 2;
    int rowBase = warpM * 32;          // warp covers rows rowBase..+31
    int colBase = warpN * 64;          // warp covers cols colBase..+63

    // gmem load assignments
    int arow = t >> 1;                 // 0..127
    int ahalf = (t & 1) * 8;           // k-offset 0 or 8
    int garow = row0 + arow;
    bool aval = garow < M;
    const float* Ap = A + (size_t)garow * K + ahalf;
    int brow = t >> 4;                 // 0..15
    int bcol = (t & 15) * 8;           // 0..120
    const float* Bp = B + (size_t)brow * N + col0 + bcol;

    float4 aR0, aR1, bR0, bR1;
    aR0 = aval ? *reinterpret_cast<const float4*>(Ap)     : make_float4(0,0,0,0);
    aR1 = aval ? *reinterpret_cast<const float4*>(Ap + 4) : make_float4(0,0,0,0);
    bR0 = *reinterpret_cast<const float4*>(Bp);
    bR1 = *reinterpret_cast<const float4*>(Bp + 4);

    float c[2][8][4];
    #pragma unroll
    for (int i = 0; i < 2; i++)
        #pragma unroll
        for (int j = 0; j < 8; j++)
            #pragma unroll
            for (int q = 0; q < 4; q++) c[i][j][q] = 0.f;

    int buf = 0;
    for (int kt = 0; kt < K; kt += 16) {
        // store prefetched chunk (converted to tf32)
        unsigned* as = &As[buf][arow * AS_STRIDE + ahalf];
        as[0] = f2tf(aR0.x); as[1] = f2tf(aR0.y); as[2] = f2tf(aR0.z); as[3] = f2tf(aR0.w);
        as[4] = f2tf(aR1.x); as[5] = f2tf(aR1.y); as[6] = f2tf(aR1.z); as[7] = f2tf(aR1.w);
        unsigned* bs = &Bs[buf][brow * BS_STRIDE + bcol];
        bs[0] = f2tf(bR0.x); bs[1] = f2tf(bR0.y); bs[2] = f2tf(bR0.z); bs[3] = f2tf(bR0.w);
        bs[4] = f2tf(bR1.x); bs[5] = f2tf(bR1.y); bs[6] = f2tf(bR1.z); bs[7] = f2tf(bR1.w);
        __syncthreads();
        if (kt + 16 < K) {
            aR0 = aval ? *reinterpret_cast<const float4*>(Ap + kt + 16)     : make_float4(0,0,0,0);
            aR1 = aval ? *reinterpret_cast<const float4*>(Ap + kt + 16 + 4) : make_float4(0,0,0,0);
            bR0 = *reinterpret_cast<const float4*>(Bp + (size_t)(kt + 16) * N);
            bR1 = *reinterpret_cast<const float4*>(Bp + (size_t)(kt + 16) * N + 4);
        }
        #pragma unroll
        for (int ks = 0; ks < 2; ks++) {
            int k0 = ks * 8;
            // A fragments for 2 m-tiles
            unsigned a[2][4];
            #pragma unroll
            for (int mt = 0; mt < 2; mt++) {
                int r = rowBase + mt * 16 + g;
                a[mt][0] = As[buf][(r    ) * AS_STRIDE + k0 + tig];
                a[mt][1] = As[buf][(r + 8) * AS_STRIDE + k0 + tig];
                a[mt][2] = As[buf][(r    ) * AS_STRIDE + k0 + tig + 4];
                a[mt][3] = As[buf][(r + 8) * AS_STRIDE + k0 + tig + 4];
            }
            #pragma unroll
            for (int nt = 0; nt < 8; nt++) {
                int n = colBase + nt * 8 + g;
                unsigned b0 = Bs[buf][(k0 + tig    ) * BS_STRIDE + n];
                unsigned b1 = Bs[buf][(k0 + tig + 4) * BS_STRIDE + n];
                #pragma unroll
                for (int mt = 0; mt < 2; mt++)
                    mma_tf32(c[mt][nt][0], c[mt][nt][1], c[mt][nt][2], c[mt][nt][3],
                             a[mt][0], a[mt][1], a[mt][2], a[mt][3], b0, b1);
            }
        }
        buf ^= 1;
    }

    // epilogue: bias+relu, store, fused logit partials
    #pragma unroll
    for (int mt = 0; mt < 2; mt++) {
        int r0 = row0 + rowBase + mt * 16 + g;   // and r0+8
        float p0 = 0.f, p1 = 0.f;
        #pragma unroll
        for (int nt = 0; nt < 8; nt++) {
            int col = col0 + colBase + nt * 8 + tig * 2;
            float o0 = c[mt][nt][0], o1 = c[mt][nt][1];
            float o2 = c[mt][nt][2], o3 = c[mt][nt][3];
            if (bias) {
                float bb0 = bias[col], bb1 = bias[col + 1];
                o0 = fmaxf(o0 + bb0, 0.f); o1 = fmaxf(o1 + bb1, 0.f);
                o2 = fmaxf(o2 + bb0, 0.f); o3 = fmaxf(o3 + bb1, 0.f);
            }
            if (r0 < M)
                *reinterpret_cast<float2*>(&C[(size_t)r0 * N + col]) = make_float2(o0, o1);
            if (r0 + 8 < M)
                *reinterpret_cast<float2*>(&C[(size_t)(r0 + 8) * N + col]) = make_float2(o2, o3);
            if (Wa) {
                float w0 = Wa[col], w1 = Wa[col + 1];
                p0 = fmaf(o0, w0, fmaf(o1, w1, p0));
                p1 = fmaf(o2, w0, fmaf(o3, w1, p1));
            }
        }
        if (Wa) {
            p0 += __shfl_xor_sync(0xffffffffu, p0, 1);
            p0 += __shfl_xor_sync(0xffffffffu, p0, 2);
            p1 += __shfl_xor_sync(0xffffffffu, p1, 1);
            p1 += __shfl_xor_sync(0xffffffffu, p1, 2);
            if (tig == 0) {
                if (r0 < M)     atomicAdd(&g_logits[r0], p0);
                if (r0 + 8 < M) atomicAdd(&g_logits[r0 + 8], p1);
            }
        }
    }
}

// ---------------- softmax: global max (order-preserving encode) ----------------
__global__ void k_maxenc() {
    int i = blockIdx.x * blockDim.x + threadIdx.x;
    unsigned u = 0u;
    if (i < N_NODES) {
        unsigned b = __float_as_uint(g_logits[i]);
        u = (b & 0x80000000u) ? ~b : (b | 0x80000000u);
    }
    #pragma unroll
    for (int off = 16; off; off >>= 1) u = max(u, __shfl_xor_sync(0xffffffffu, u, off));
    if ((threadIdx.x & 31) == 0) atomicMax(&g_max_enc, u);
}

// ---------------- exp weights (one expf per node) + weight sum ----------------
__global__ void k_expw() {
    int i = blockIdx.x * blockDim.x + threadIdx.x;
    unsigned u = g_max_enc;
    float m = (u & 0x80000000u) ? __uint_as_float(u & 0x7FFFFFFFu) : __uint_as_float(~u);
    float w = 0.f;
    if (i < N_NODES) {
        w = expf(g_logits[i] - m);
        g_logits[i] = w;
    }
    #pragma unroll
    for (int off = 16; off; off >>= 1) w += __shfl_xor_sync(0xffffffffu, w, off);
    if ((threadIdx.x & 31) == 0) atomicAdd(&g_wsum, w);
}

// ---------------- weighted pooling ----------------
__global__ void k_pool(const float* __restrict__ h2) {
    int f = threadIdx.x;  // 256 threads = 256 features
    float acc = 0.f;
    for (int r = blockIdx.x; r < N_NODES; r += gridDim.x)
        acc = fmaf(h2[(size_t)r * OUT_DIM + f], g_logits[r], acc);
    atomicAdd(&g_gacc[f], acc);
}

__global__ void k_finish(float* __restrict__ out_tail) {
    int f = threadIdx.x;
    if (f < OUT_DIM) out_tail[f] = g_gacc[f] / g_wsum;
}

// ---------------- launch ----------------
extern "C" void kernel_launch(void* const* d_in, const int* in_sizes, int n_in,
                              void* d_out, int out_size) {
    const float* x  = (const float*)d_in[0];
    const void*  ei = d_in[1];
    const float* W1 = (const float*)d_in[2];
    const float* b1 = (const float*)d_in[3];
    const float* W2 = (const float*)d_in[4];
    const float* b2 = (const float*)d_in[5];
    const float* Wa = (const float*)d_in[6];
    float* out = (float*)d_out;

    float *bufA, *bufB;
    cudaGetSymbolAddress((void**)&bufA, g_bufA);
    cudaGetSymbolAddress((void**)&bufB, g_bufB);

    // one-time resources (created on the non-captured correctness call)
    static cudaStream_t s2 = nullptr;
    static cudaEvent_t evFork = nullptr, evJoin = nullptr;
    if (!s2) {
        cudaStreamCreateWithFlags(&s2, cudaStreamNonBlocking);
        cudaEventCreateWithFlags(&evFork, cudaEventDisableTiming);
        cudaEventCreateWithFlags(&evJoin, cudaEventDisableTiming);
    }

    // fork: CSR build on s2, GEMM1 (x@W1) on main stream
    cudaEventRecord(evFork, 0);
    cudaStreamWaitEvent(s2, evFork, 0);

    k_init<<<NBLK, 256, 0, s2>>>((const int*)ei);
    k_count<<<(N_EDGES + 255) / 256, 256, 0, s2>>>(ei);
    k_scanA<<<NBLK, 256, 0, s2>>>();
    k_scanC<<<NBLK, 256, 0, s2>>>();
    k_fill<<<(N_EDGES + 255) / 256, 256, 0, s2>>>(ei);
    cudaEventRecord(evJoin, s2);

    {   // GEMM1 raw: bufB = x @ W1   (layer1 re-associated: relu(Agg(xW1)+b1))
        dim3 grid((N_NODES + 127) / 128, F_DIM / 128);
        k_gemm<<<grid, 256>>>(x, W1, nullptr, bufB, N_NODES, F_DIM, nullptr);
    }
    cudaStreamWaitEvent(0, evJoin, 0);

    // layer 1 aggregation with fused bias+relu: bufA = h1
    k_agg<<<(N_NODES * 32 + 255) / 256, 256>>>(bufB, bufA, b1);
    // layer 2: agg (raw) then GEMM with bias+relu+logits
    k_agg<<<(N_NODES * 32 + 255) / 256, 256>>>(bufA, bufB, nullptr);
    {
        dim3 grid((N_NODES + 127) / 128, OUT_DIM / 128);
        k_gemm<<<grid, 256>>>(bufB, W2, b2, out, N_NODES, OUT_DIM, Wa);
    }
    // softmax-weighted pooling
    k_maxenc<<<NBLK, 256>>>();
    k_expw<<<NBLK, 256>>>();
    k_pool<<<592, 256>>>(out);
    k_finish<<<1, 256>>>(out + (size_t)N_NODES * OUT_DIM);
}

// round 10
// speedup vs baseline: 2.2443x; 1.0982x over previous
#include <cuda_runtime.h>
#include <cuda_fp16.h>
#include <math.h>

#define N_NODES 50000
#define N_EDGES 800000
#define F_DIM   128
#define OUT_DIM 256
#define NBLK    196   // ceil(50000/256)

// ---------------- device scratch (no allocations allowed) ----------------
__device__ float    g_bufA[(size_t)N_NODES * F_DIM];   // reused as fp16 (half capacity)
__device__ float    g_bufB[(size_t)N_NODES * F_DIM];
__device__ int      g_cnt[N_NODES];
__device__ int      g_rowptr[N_NODES + 1];
__device__ int      g_cursor[N_NODES];
__device__ int      g_col[N_EDGES];
__device__ float    g_dinv[N_NODES];
__device__ float    g_logits[N_NODES];   // raw logits, then exp weights
__device__ int      g_part[NBLK];
__device__ unsigned g_max_enc;
__device__ float    g_wsum;
__device__ float    g_gacc[OUT_DIM];
__device__ unsigned g_poolctr;
__device__ int      g_is64;

// ---------------- helpers ----------------
__device__ __forceinline__ int edge_src(const void* ei, int e) {
    return g_is64 ? (int)((const long long*)ei)[e] : ((const int*)ei)[e];
}
__device__ __forceinline__ int edge_dst(const void* ei, int e) {
    return g_is64 ? (int)((const long long*)ei)[(size_t)N_EDGES + e]
                  : ((const int*)ei)[(size_t)N_EDGES + e];
}
__device__ __forceinline__ unsigned f2tf(float f) {
    unsigned r;
    asm("cvt.rna.tf32.f32 %0, %1;" : "=r"(r) : "f"(f));
    return r;
}
__device__ __forceinline__ void mma_tf32(float& c0, float& c1, float& c2, float& c3,
                                         unsigned a0, unsigned a1, unsigned a2, unsigned a3,
                                         unsigned b0, unsigned b1) {
    asm volatile("mma.sync.aligned.m16n8k8.row.col.f32.tf32.tf32.f32 "
                 "{%0,%1,%2,%3}, {%4,%5,%6,%7}, {%8,%9}, {%0,%1,%2,%3};"
                 : "+f"(c0), "+f"(c1), "+f"(c2), "+f"(c3)
                 : "r"(a0), "r"(a1), "r"(a2), "r"(a3), "r"(b0), "r"(b1));
}

// ---------------- init: zero cnt + gacc/scalars + dtype detect ----------------
__global__ void k_init(const int* __restrict__ ei32) {
    int i = blockIdx.x * 256 + threadIdx.x;
    if (i < N_NODES) g_cnt[i] = 0;
    if (blockIdx.x == 0) {
        g_gacc[threadIdx.x] = 0.f;
        if (threadIdx.x == 0) {
            g_wsum = 0.f; g_max_enc = 0u; g_poolctr = 0u;
            g_rowptr[N_NODES] = N_EDGES;
            int ornz = 0;
            #pragma unroll 8
            for (int k = 0; k < 256; k++) ornz |= ei32[2 * k + 1];
            g_is64 = (ornz == 0) ? 1 : 0;
        }
    }
}

// ---------------- degree histogram ----------------
__global__ void k_count(const void* __restrict__ ei) {
    int e = blockIdx.x * blockDim.x + threadIdx.x;
    if (e >= N_EDGES) return;
    atomicAdd(&g_cnt[edge_dst(ei, e)], 1);
}

// ---------------- scanA: block sums + dinv + zero cursor/logits ----------------
__global__ void k_scanA() {
    __shared__ int sh[256];
    int t = threadIdx.x;
    int i = blockIdx.x * 256 + t;
    int v = (i < N_NODES) ? g_cnt[i] : 0;
    if (i < N_NODES) {
        g_dinv[i] = rsqrtf((float)(v + 1));  // +1 self-loop
        g_cursor[i] = 0;
        g_logits[i] = 0.f;
    }
    sh[t] = v; __syncthreads();
    #pragma unroll
    for (int off = 128; off; off >>= 1) {
        if (t < off) sh[t] += sh[t + off];
        __syncthreads();
    }
    if (t == 0) g_part[blockIdx.x] = sh[0];
}

// ---------------- scanC: redundant partial-scan per block + final rowptr -------
__global__ void k_scanC() {
    __shared__ int shp[256];
    __shared__ int sh[256];
    __shared__ int base;
    int t = threadIdx.x;
    int pv = (t < NBLK) ? g_part[t] : 0;
    shp[t] = pv; __syncthreads();
    #pragma unroll
    for (int off = 1; off < 256; off <<= 1) {
        int u = (t >= off) ? shp[t - off] : 0;
        __syncthreads();
        shp[t] += u;
        __syncthreads();
    }
    if (t == (int)blockIdx.x) base = shp[t] - pv;
    int i = blockIdx.x * 256 + t;
    int v = (i < N_NODES) ? g_cnt[i] : 0;
    sh[t] = v; __syncthreads();
    #pragma unroll
    for (int off = 1; off < 256; off <<= 1) {
        int u = (t >= off) ? sh[t - off] : 0;
        __syncthreads();
        sh[t] += u;
        __syncthreads();
    }
    if (i < N_NODES) g_rowptr[i] = base + sh[t] - v;
}

__global__ void k_fill(const void* __restrict__ ei) {
    int e = blockIdx.x * blockDim.x + threadIdx.x;
    if (e >= N_EDGES) return;
    int s = edge_src(ei, e);
    int d = edge_dst(ei, e);
    int pos = g_rowptr[d] + atomicAdd(&g_cursor[d], 1);
    g_col[pos] = s;
}

// ---------------- GCN aggregation (fp16 features): one warp per node ------------
// out[i] = dinv_i * sum_j dinv_j * in[j]  +  dinv_i^2 * in[i]   (+bias, relu opt)
__global__ void k_agg_h(const __half* __restrict__ in, __half* __restrict__ out,
                        const float* __restrict__ bias) {
    int node = (blockIdx.x * blockDim.x + threadIdx.x) >> 5;
    if (node >= N_NODES) return;
    int lane = threadIdx.x & 31;
    const uint2* inv = reinterpret_cast<const uint2*>(in);  // 8B = 4 halves per lane
    float di = g_dinv[node];
    uint2 raw = inv[(size_t)node * 32 + lane];
    __half2 h0 = *reinterpret_cast<__half2*>(&raw.x);
    __half2 h1 = *reinterpret_cast<__half2*>(&raw.y);
    float2 f0 = __half22float2(h0), f1 = __half22float2(h1);
    float sw = di * di;
    float a0 = f0.x * sw, a1 = f0.y * sw, a2 = f1.x * sw, a3 = f1.y * sw;
    int p = g_rowptr[node], end = g_rowptr[node + 1];
    for (; p + 4 <= end; p += 4) {
        int s0 = g_col[p], s1 = g_col[p + 1], s2 = g_col[p + 2], s3 = g_col[p + 3];
        uint2 r0 = inv[(size_t)s0 * 32 + lane];
        uint2 r1 = inv[(size_t)s1 * 32 + lane];
        uint2 r2 = inv[(size_t)s2 * 32 + lane];
        uint2 r3 = inv[(size_t)s3 * 32 + lane];
        float w0 = g_dinv[s0] * di, w1 = g_dinv[s1] * di;
        float w2 = g_dinv[s2] * di, w3 = g_dinv[s3] * di;
        #pragma unroll
        for (int q = 0; q < 4; q++) {
            uint2 rr = (q == 0) ? r0 : (q == 1) ? r1 : (q == 2) ? r2 : r3;
            float w = (q == 0) ? w0 : (q == 1) ? w1 : (q == 2) ? w2 : w3;
            float2 u0 = __half22float2(*reinterpret_cast<__half2*>(&rr.x));
            float2 u1 = __half22float2(*reinterpret_cast<__half2*>(&rr.y));
            a0 = fmaf(u0.x, w, a0);
            a1 = fmaf(u0.y, w, a1);
            a2 = fmaf(u1.x, w, a2);
            a3 = fmaf(u1.y, w, a3);
        }
    }
    for (; p < end; ++p) {
        int s = g_col[p];
        float w = g_dinv[s] * di;
        uint2 rr = inv[(size_t)s * 32 + lane];
        float2 u0 = __half22float2(*reinterpret_cast<__half2*>(&rr.x));
        float2 u1 = __half22float2(*reinterpret_cast<__half2*>(&rr.y));
        a0 = fmaf(u0.x, w, a0);
        a1 = fmaf(u0.y, w, a1);
        a2 = fmaf(u1.x, w, a2);
        a3 = fmaf(u1.y, w, a3);
    }
    if (bias) {
        float4 bv = reinterpret_cast<const float4*>(bias)[lane];
        a0 = fmaxf(a0 + bv.x, 0.f);
        a1 = fmaxf(a1 + bv.y, 0.f);
        a2 = fmaxf(a2 + bv.z, 0.f);
        a3 = fmaxf(a3 + bv.w, 0.f);
    }
    __half2 o0 = __floats2half2_rn(a0, a1);
    __half2 o1 = __floats2half2_rn(a2, a3);
    uint2 st;
    st.x = *reinterpret_cast<unsigned*>(&o0);
    st.y = *reinterpret_cast<unsigned*>(&o1);
    reinterpret_cast<uint2*>(out)[(size_t)node * 32 + lane] = st;
}

// ---------------- TF32 tensor-core GEMM: 128x128 tile, K=128, kchunk=16,
//                  A fp32 or fp16, output fp32 or fp16, optional bias+relu+Wa ----
#define AS_STRIDE 20
#define BS_STRIDE 136
template<bool AHALF, bool OUTHALF>
__global__ __launch_bounds__(256, 2) void k_gemm(
    const void* __restrict__ Avoid, const float* __restrict__ B,
    const float* __restrict__ bias, void* __restrict__ Cvoid, int M, int N,
    const float* __restrict__ Wa) {
    const int K = 128;
    __shared__ unsigned As[2][128 * AS_STRIDE];
    __shared__ unsigned Bs[2][16 * BS_STRIDE];

    int t = threadIdx.x;
    int lane = t & 31;
    int warp = t >> 5;
    int g = lane >> 2, tig = lane & 3;
    int row0 = blockIdx.x * 128;
    int col0 = blockIdx.y * 128;
    int warpM = warp & 3, warpN = warp >> 2;
    int rowBase = warpM * 32;
    int colBase = warpN * 64;

    int arow = t >> 1;
    int ahalf = (t & 1) * 8;
    int garow = row0 + arow;
    bool aval = garow < M;
    const float*  Apf = (const float*)Avoid + (size_t)garow * K + ahalf;
    const __half* Aph = (const __half*)Avoid + (size_t)garow * K + ahalf;
    int brow = t >> 4;
    int bcol = (t & 15) * 8;
    const float* Bp = B + (size_t)brow * N + col0 + bcol;

    float4 aR0, aR1;
    uint4 aRh;
    if (AHALF) {
        aRh = aval ? *reinterpret_cast<const uint4*>(Aph) : make_uint4(0, 0, 0, 0);
    } else {
        aR0 = aval ? *reinterpret_cast<const float4*>(Apf)     : make_float4(0, 0, 0, 0);
        aR1 = aval ? *reinterpret_cast<const float4*>(Apf + 4) : make_float4(0, 0, 0, 0);
    }
    float4 bR0 = *reinterpret_cast<const float4*>(Bp);
    float4 bR1 = *reinterpret_cast<const float4*>(Bp + 4);

    float c[2][8][4];
    #pragma unroll
    for (int i = 0; i < 2; i++)
        #pragma unroll
        for (int j = 0; j < 8; j++)
            #pragma unroll
            for (int q = 0; q < 4; q++) c[i][j][q] = 0.f;

    int buf = 0;
    for (int kt = 0; kt < K; kt += 16) {
        unsigned* as = &As[buf][arow * AS_STRIDE + ahalf];
        if (AHALF) {
            // fp16 -> fp32 bits are already valid tf32 (10-bit mantissa), no cvt needed
            #pragma unroll
            for (int q = 0; q < 4; q++) {
                unsigned rw = (q == 0) ? aRh.x : (q == 1) ? aRh.y : (q == 2) ? aRh.z : aRh.w;
                float2 f = __half22float2(*reinterpret_cast<__half2*>(&rw));
                as[2 * q]     = __float_as_uint(f.x);
                as[2 * q + 1] = __float_as_uint(f.y);
            }
        } else {
            as[0] = f2tf(aR0.x); as[1] = f2tf(aR0.y); as[2] = f2tf(aR0.z); as[3] = f2tf(aR0.w);
            as[4] = f2tf(aR1.x); as[5] = f2tf(aR1.y); as[6] = f2tf(aR1.z); as[7] = f2tf(aR1.w);
        }
        unsigned* bs = &Bs[buf][brow * BS_STRIDE + bcol];
        bs[0] = f2tf(bR0.x); bs[1] = f2tf(bR0.y); bs[2] = f2tf(bR0.z); bs[3] = f2tf(bR0.w);
        bs[4] = f2tf(bR1.x); bs[5] = f2tf(bR1.y); bs[6] = f2tf(bR1.z); bs[7] = f2tf(bR1.w);
        __syncthreads();
        if (kt + 16 < K) {
            if (AHALF) {
                aRh = aval ? *reinterpret_cast<const uint4*>(Aph + kt + 16)
                           : make_uint4(0, 0, 0, 0);
            } else {
                aR0 = aval ? *reinterpret_cast<const float4*>(Apf + kt + 16)
                           : make_float4(0, 0, 0, 0);
                aR1 = aval ? *reinterpret_cast<const float4*>(Apf + kt + 16 + 4)
                           : make_float4(0, 0, 0, 0);
            }
            bR0 = *reinterpret_cast<const float4*>(Bp + (size_t)(kt + 16) * N);
            bR1 = *reinterpret_cast<const float4*>(Bp + (size_t)(kt + 16) * N + 4);
        }
        #pragma unroll
        for (int ks = 0; ks < 2; ks++) {
            int k0 = ks * 8;
            unsigned a[2][4];
            #pragma unroll
            for (int mt = 0; mt < 2; mt++) {
                int r = rowBase + mt * 16 + g;
                a[mt][0] = As[buf][(r    ) * AS_STRIDE + k0 + tig];
                a[mt][1] = As[buf][(r + 8) * AS_STRIDE + k0 + tig];
                a[mt][2] = As[buf][(r    ) * AS_STRIDE + k0 + tig + 4];
                a[mt][3] = As[buf][(r + 8) * AS_STRIDE + k0 + tig + 4];
            }
            #pragma unroll
            for (int nt = 0; nt < 8; nt++) {
                int n = colBase + nt * 8 + g;
                unsigned b0 = Bs[buf][(k0 + tig    ) * BS_STRIDE + n];
                unsigned b1 = Bs[buf][(k0 + tig + 4) * BS_STRIDE + n];
                #pragma unroll
                for (int mt = 0; mt < 2; mt++)
                    mma_tf32(c[mt][nt][0], c[mt][nt][1], c[mt][nt][2], c[mt][nt][3],
                             a[mt][0], a[mt][1], a[mt][2], a[mt][3], b0, b1);
            }
        }
        buf ^= 1;
    }

    float*  Cf = (float*)Cvoid;
    __half* Ch = (__half*)Cvoid;
    #pragma unroll
    for (int mt = 0; mt < 2; mt++) {
        int r0 = row0 + rowBase + mt * 16 + g;   // and r0+8
        float p0 = 0.f, p1 = 0.f;
        #pragma unroll
        for (int nt = 0; nt < 8; nt++) {
            int col = col0 + colBase + nt * 8 + tig * 2;
            float o0 = c[mt][nt][0], o1 = c[mt][nt][1];
            float o2 = c[mt][nt][2], o3 = c[mt][nt][3];
            if (bias) {
                float bb0 = bias[col], bb1 = bias[col + 1];
                o0 = fmaxf(o0 + bb0, 0.f); o1 = fmaxf(o1 + bb1, 0.f);
                o2 = fmaxf(o2 + bb0, 0.f); o3 = fmaxf(o3 + bb1, 0.f);
            }
            if (OUTHALF) {
                __half2 ho = __floats2half2_rn(o0, o1);
                __half2 hp = __floats2half2_rn(o2, o3);
                if (r0 < M)
                    *reinterpret_cast<__half2*>(&Ch[(size_t)r0 * N + col]) = ho;
                if (r0 + 8 < M)
                    *reinterpret_cast<__half2*>(&Ch[(size_t)(r0 + 8) * N + col]) = hp;
            } else {
                if (r0 < M)
                    *reinterpret_cast<float2*>(&Cf[(size_t)r0 * N + col]) = make_float2(o0, o1);
                if (r0 + 8 < M)
                    *reinterpret_cast<float2*>(&Cf[(size_t)(r0 + 8) * N + col]) = make_float2(o2, o3);
            }
            if (Wa) {
                float w0 = Wa[col], w1 = Wa[col + 1];
                p0 = fmaf(o0, w0, fmaf(o1, w1, p0));
                p1 = fmaf(o2, w0, fmaf(o3, w1, p1));
            }
        }
        if (Wa) {
            p0 += __shfl_xor_sync(0xffffffffu, p0, 1);
            p0 += __shfl_xor_sync(0xffffffffu, p0, 2);
            p1 += __shfl_xor_sync(0xffffffffu, p1, 1);
            p1 += __shfl_xor_sync(0xffffffffu, p1, 2);
            if (tig == 0) {
                if (r0 < M)     atomicAdd(&g_logits[r0], p0);
                if (r0 + 8 < M) atomicAdd(&g_logits[r0 + 8], p1);
            }
        }
    }
}

// ---------------- softmax: global max (order-preserving encode) ----------------
__global__ void k_maxenc() {
    int i = blockIdx.x * blockDim.x + threadIdx.x;
    unsigned u = 0u;
    if (i < N_NODES) {
        unsigned b = __float_as_uint(g_logits[i]);
        u = (b & 0x80000000u) ? ~b : (b | 0x80000000u);
    }
    #pragma unroll
    for (int off = 16; off; off >>= 1) u = max(u, __shfl_xor_sync(0xffffffffu, u, off));
    if ((threadIdx.x & 31) == 0) atomicMax(&g_max_enc, u);
}

// ---------------- exp weights (one expf per node) + weight sum ----------------
__global__ void k_expw() {
    int i = blockIdx.x * blockDim.x + threadIdx.x;
    unsigned u = g_max_enc;
    float m = (u & 0x80000000u) ? __uint_as_float(u & 0x7FFFFFFFu) : __uint_as_float(~u);
    float w = 0.f;
    if (i < N_NODES) {
        w = expf(g_logits[i] - m);
        g_logits[i] = w;
    }
    #pragma unroll
    for (int off = 16; off; off >>= 1) w += __shfl_xor_sync(0xffffffffu, w, off);
    if ((threadIdx.x & 31) == 0) atomicAdd(&g_wsum, w);
}

// ---------------- weighted pooling + fused finish (last-block reduction) -------
__global__ void k_pool(const float* __restrict__ h2, float* __restrict__ out_tail) {
    __shared__ bool amLast;
    int f = threadIdx.x;  // 256 threads = 256 features
    float acc = 0.f;
    for (int r = blockIdx.x; r < N_NODES; r += gridDim.x)
        acc = fmaf(h2[(size_t)r * OUT_DIM + f], g_logits[r], acc);
    atomicAdd(&g_gacc[f], acc);
    __threadfence();
    if (f == 0) {
        unsigned done = atomicAdd(&g_poolctr, 1u);
        amLast = (done == gridDim.x - 1);
    }
    __syncthreads();
    if (amLast) {
        float v = __ldcg(&g_gacc[f]);   // L2 read: sees all blocks' atomics
        out_tail[f] = v / g_wsum;
    }
}

// ---------------- launch ----------------
extern "C" void kernel_launch(void* const* d_in, const int* in_sizes, int n_in,
                              void* d_out, int out_size) {
    const float* x  = (const float*)d_in[0];
    const void*  ei = d_in[1];
    const float* W1 = (const float*)d_in[2];
    const float* b1 = (const float*)d_in[3];
    const float* W2 = (const float*)d_in[4];
    const float* b2 = (const float*)d_in[5];
    const float* Wa = (const float*)d_in[6];
    float* out = (float*)d_out;

    float *bufA, *bufB;
    cudaGetSymbolAddress((void**)&bufA, g_bufA);
    cudaGetSymbolAddress((void**)&bufB, g_bufB);
    __half* hA = (__half*)bufA;
    __half* hB = (__half*)bufB;

    // one-time resources (created on the non-captured correctness call)
    static cudaStream_t s2 = nullptr;
    static cudaEvent_t evFork = nullptr, evJoin = nullptr;
    if (!s2) {
        cudaStreamCreateWithFlags(&s2, cudaStreamNonBlocking);
        cudaEventCreateWithFlags(&evFork, cudaEventDisableTiming);
        cudaEventCreateWithFlags(&evJoin, cudaEventDisableTiming);
    }

    // fork: CSR build on s2, GEMM1 (x@W1 -> fp16) on main stream
    cudaEventRecord(evFork, 0);
    cudaStreamWaitEvent(s2, evFork, 0);

    k_init<<<NBLK, 256, 0, s2>>>((const int*)ei);
    k_count<<<(N_EDGES + 255) / 256, 256, 0, s2>>>(ei);
    k_scanA<<<NBLK, 256, 0, s2>>>();
    k_scanC<<<NBLK, 256, 0, s2>>>();
    k_fill<<<(N_EDGES + 255) / 256, 256, 0, s2>>>(ei);
    cudaEventRecord(evJoin, s2);

    {   // GEMM1 raw: hB = fp16(x @ W1)   (layer1 re-associated: relu(Agg(xW1)+b1))
        dim3 grid((N_NODES + 127) / 128, F_DIM / 128);
        k_gemm<false, true><<<grid, 256>>>(x, W1, nullptr, hB, N_NODES, F_DIM, nullptr);
    }
    cudaStreamWaitEvent(0, evJoin, 0);

    // layer 1 aggregation with fused bias+relu: hA = h1 (fp16)
    k_agg_h<<<(N_NODES * 32 + 255) / 256, 256>>>(hB, hA, b1);
    // layer 2: agg (raw, fp16) then GEMM (fp16 A) with bias+relu+logits -> fp32 out
    k_agg_h<<<(N_NODES * 32 + 255) / 256, 256>>>(hA, hB, nullptr);
    {
        dim3 grid((N_NODES + 127) / 128, OUT_DIM / 128);
        k_gemm<true, false><<<grid, 256>>>(hB, W2, b2, out, N_NODES, OUT_DIM, Wa);
    }
    // softmax-weighted pooling (finish fused into pool)
    k_maxenc<<<NBLK, 256>>>();
    k_expw<<<NBLK, 256>>>();
    k_pool<<<592, 256>>>(out, out + (size_t)N_NODES * OUT_DIM);
}

// round 11
// speedup vs baseline: 2.4090x; 1.0734x over previous
#include <cuda_runtime.h>
#include <cuda_fp16.h>
#include <math.h>

#define N_NODES 50000
#define N_EDGES 800000
#define F_DIM   128
#define OUT_DIM 256
#define NBLK    196   // ceil(50000/256)

// ---------------- device scratch (no allocations allowed) ----------------
__device__ float    g_bufA[(size_t)N_NODES * F_DIM];   // reused as fp16
__device__ float    g_bufB[(size_t)N_NODES * F_DIM];
__device__ int      g_cnt[N_NODES];          // zero-init at load; re-zeroed by scanC
__device__ int      g_rowptr[N_NODES + 1];
__device__ int      g_cursor[N_NODES];
__device__ int      g_col[N_EDGES];
__device__ float    g_dinv[N_NODES];
__device__ float    g_logits[N_NODES];
__device__ int      g_part[NBLK];
__device__ unsigned g_max_enc;
__device__ float    g_wsum;
__device__ float    g_gacc[OUT_DIM];
__device__ unsigned g_poolctr;
__device__ int      g_is64;

// ---------------- helpers ----------------
__device__ __forceinline__ int edge_src(const void* ei, int e) {
    return g_is64 ? (int)((const long long*)ei)[e] : ((const int*)ei)[e];
}
__device__ __forceinline__ int edge_dst(const void* ei, int e) {
    return g_is64 ? (int)((const long long*)ei)[(size_t)N_EDGES + e]
                  : ((const int*)ei)[(size_t)N_EDGES + e];
}
__device__ __forceinline__ unsigned f2tf(float f) {
    unsigned r;
    asm("cvt.rna.tf32.f32 %0, %1;" : "=r"(r) : "f"(f));
    return r;
}
__device__ __forceinline__ void mma_tf32(float& c0, float& c1, float& c2, float& c3,
                                         unsigned a0, unsigned a1, unsigned a2, unsigned a3,
                                         unsigned b0, unsigned b1) {
    asm volatile("mma.sync.aligned.m16n8k8.row.col.f32.tf32.tf32.f32 "
                 "{%0,%1,%2,%3}, {%4,%5,%6,%7}, {%8,%9}, {%0,%1,%2,%3};"
                 : "+f"(c0), "+f"(c1), "+f"(c2), "+f"(c3)
                 : "r"(a0), "r"(a1), "r"(a2), "r"(a3), "r"(b0), "r"(b1));
}

// ---------------- init: scalars + gacc + dtype detect (1 block) ----------------
__global__ void k_init(const int* __restrict__ ei32) {
    g_gacc[threadIdx.x] = 0.f;
    if (threadIdx.x == 0) {
        g_wsum = 0.f; g_max_enc = 0u; g_poolctr = 0u;
        g_rowptr[N_NODES] = N_EDGES;
        int ornz = 0;
        #pragma unroll 8
        for (int k = 0; k < 256; k++) ornz |= ei32[2 * k + 1];
        g_is64 = (ornz == 0) ? 1 : 0;
    }
}

// ---------------- degree histogram (cnt pre-zeroed by load-init / prior scanC) --
__global__ void k_count(const void* __restrict__ ei) {
    int e = blockIdx.x * blockDim.x + threadIdx.x;
    if (e >= N_EDGES) return;
    atomicAdd(&g_cnt[edge_dst(ei, e)], 1);
}

// ---------------- scanA: block sums + dinv + zero cursor/logits ----------------
__global__ void k_scanA() {
    __shared__ int sh[256];
    int t = threadIdx.x;
    int i = blockIdx.x * 256 + t;
    int v = (i < N_NODES) ? g_cnt[i] : 0;
    if (i < N_NODES) {
        g_dinv[i] = rsqrtf((float)(v + 1));  // +1 self-loop
        g_cursor[i] = 0;
        g_logits[i] = 0.f;
    }
    sh[t] = v; __syncthreads();
    #pragma unroll
    for (int off = 128; off; off >>= 1) {
        if (t < off) sh[t] += sh[t + off];
        __syncthreads();
    }
    if (t == 0) g_part[blockIdx.x] = sh[0];
}

// ---------------- scanC: rowptr + re-zero cnt for next replay ------------------
__global__ void k_scanC() {
    __shared__ int shp[256];
    __shared__ int sh[256];
    __shared__ int base;
    int t = threadIdx.x;
    int pv = (t < NBLK) ? g_part[t] : 0;
    shp[t] = pv; __syncthreads();
    #pragma unroll
    for (int off = 1; off < 256; off <<= 1) {
        int u = (t >= off) ? shp[t - off] : 0;
        __syncthreads();
        shp[t] += u;
        __syncthreads();
    }
    if (t == (int)blockIdx.x) base = shp[t] - pv;
    int i = blockIdx.x * 256 + t;
    int v = (i < N_NODES) ? g_cnt[i] : 0;
    if (i < N_NODES) g_cnt[i] = 0;           // cnt consumed — clean for next replay
    sh[t] = v; __syncthreads();
    #pragma unroll
    for (int off = 1; off < 256; off <<= 1) {
        int u = (t >= off) ? sh[t - off] : 0;
        __syncthreads();
        sh[t] += u;
        __syncthreads();
    }
    if (i < N_NODES) g_rowptr[i] = base + sh[t] - v;
}

__global__ void k_fill(const void* __restrict__ ei) {
    int e = blockIdx.x * blockDim.x + threadIdx.x;
    if (e >= N_EDGES) return;
    int s = edge_src(ei, e);
    int d = edge_dst(ei, e);
    int pos = g_rowptr[d] + atomicAdd(&g_cursor[d], 1);
    g_col[pos] = s;
}

// ---------------- GCN aggregation (fp16): one warp per node, unroll-8 ----------
__global__ void k_agg_h(const __half* __restrict__ in, __half* __restrict__ out,
                        const float* __restrict__ bias) {
    int node = (blockIdx.x * blockDim.x + threadIdx.x) >> 5;
    if (node >= N_NODES) return;
    int lane = threadIdx.x & 31;
    const uint2* inv = reinterpret_cast<const uint2*>(in);  // 8B = 4 halves/lane
    float di = __ldg(&g_dinv[node]);
    uint2 raw = inv[(size_t)node * 32 + lane];
    float2 f0 = __half22float2(*reinterpret_cast<__half2*>(&raw.x));
    float2 f1 = __half22float2(*reinterpret_cast<__half2*>(&raw.y));
    float sw = di * di;
    float a0 = f0.x * sw, a1 = f0.y * sw, a2 = f1.x * sw, a3 = f1.y * sw;
    int p = g_rowptr[node], end = g_rowptr[node + 1];
    for (; p + 8 <= end; p += 8) {
        int s[8]; uint2 rr[8]; float w[8];
        #pragma unroll
        for (int q = 0; q < 8; q++) s[q] = __ldg(&g_col[p + q]);
        #pragma unroll
        for (int q = 0; q < 8; q++) rr[q] = inv[(size_t)s[q] * 32 + lane];
        #pragma unroll
        for (int q = 0; q < 8; q++) w[q] = __ldg(&g_dinv[s[q]]) * di;
        #pragma unroll
        for (int q = 0; q < 8; q++) {
            float2 u0 = __half22float2(*reinterpret_cast<__half2*>(&rr[q].x));
            float2 u1 = __half22float2(*reinterpret_cast<__half2*>(&rr[q].y));
            a0 = fmaf(u0.x, w[q], a0);
            a1 = fmaf(u0.y, w[q], a1);
            a2 = fmaf(u1.x, w[q], a2);
            a3 = fmaf(u1.y, w[q], a3);
        }
    }
    for (; p < end; ++p) {
        int s = __ldg(&g_col[p]);
        float w = __ldg(&g_dinv[s]) * di;
        uint2 rr = inv[(size_t)s * 32 + lane];
        float2 u0 = __half22float2(*reinterpret_cast<__half2*>(&rr.x));
        float2 u1 = __half22float2(*reinterpret_cast<__half2*>(&rr.y));
        a0 = fmaf(u0.x, w, a0);
        a1 = fmaf(u0.y, w, a1);
        a2 = fmaf(u1.x, w, a2);
        a3 = fmaf(u1.y, w, a3);
    }
    if (bias) {
        float4 bv = reinterpret_cast<const float4*>(bias)[lane];
        a0 = fmaxf(a0 + bv.x, 0.f);
        a1 = fmaxf(a1 + bv.y, 0.f);
        a2 = fmaxf(a2 + bv.z, 0.f);
        a3 = fmaxf(a3 + bv.w, 0.f);
    }
    __half2 o0 = __floats2half2_rn(a0, a1);
    __half2 o1 = __floats2half2_rn(a2, a3);
    uint2 st;
    st.x = *reinterpret_cast<unsigned*>(&o0);
    st.y = *reinterpret_cast<unsigned*>(&o1);
    reinterpret_cast<uint2*>(out)[(size_t)node * 32 + lane] = st;
}

// ---------------- TF32 tensor-core GEMM (as R10) --------------------------------
#define AS_STRIDE 20
#define BS_STRIDE 136
template<bool AHALF, bool OUTHALF>
__global__ __launch_bounds__(256, 2) void k_gemm(
    const void* __restrict__ Avoid, const float* __restrict__ B,
    const float* __restrict__ bias, void* __restrict__ Cvoid, int M, int N,
    const float* __restrict__ Wa) {
    const int K = 128;
    __shared__ unsigned As[2][128 * AS_STRIDE];
    __shared__ unsigned Bs[2][16 * BS_STRIDE];

    int t = threadIdx.x;
    int lane = t & 31;
    int warp = t >> 5;
    int g = lane >> 2, tig = lane & 3;
    int row0 = blockIdx.x * 128;
    int col0 = blockIdx.y * 128;
    int warpM = warp & 3, warpN = warp >> 2;
    int rowBase = warpM * 32;
    int colBase = warpN * 64;

    int arow = t >> 1;
    int ahalf = (t & 1) * 8;
    int garow = row0 + arow;
    bool aval = garow < M;
    const float*  Apf = (const float*)Avoid + (size_t)garow * K + ahalf;
    const __half* Aph = (const __half*)Avoid + (size_t)garow * K + ahalf;
    int brow = t >> 4;
    int bcol = (t & 15) * 8;
    const float* Bp = B + (size_t)brow * N + col0 + bcol;

    float4 aR0, aR1;
    uint4 aRh;
    if (AHALF) {
        aRh = aval ? *reinterpret_cast<const uint4*>(Aph) : make_uint4(0, 0, 0, 0);
    } else {
        aR0 = aval ? *reinterpret_cast<const float4*>(Apf)     : make_float4(0, 0, 0, 0);
        aR1 = aval ? *reinterpret_cast<const float4*>(Apf + 4) : make_float4(0, 0, 0, 0);
    }
    float4 bR0 = *reinterpret_cast<const float4*>(Bp);
    float4 bR1 = *reinterpret_cast<const float4*>(Bp + 4);

    float c[2][8][4];
    #pragma unroll
    for (int i = 0; i < 2; i++)
        #pragma unroll
        for (int j = 0; j < 8; j++)
            #pragma unroll
            for (int q = 0; q < 4; q++) c[i][j][q] = 0.f;

    int buf = 0;
    for (int kt = 0; kt < K; kt += 16) {
        unsigned* as = &As[buf][arow * AS_STRIDE + ahalf];
        if (AHALF) {
            #pragma unroll
            for (int q = 0; q < 4; q++) {
                unsigned rw = (q == 0) ? aRh.x : (q == 1) ? aRh.y : (q == 2) ? aRh.z : aRh.w;
                float2 f = __half22float2(*reinterpret_cast<__half2*>(&rw));
                as[2 * q]     = __float_as_uint(f.x);
                as[2 * q + 1] = __float_as_uint(f.y);
            }
        } else {
            as[0] = f2tf(aR0.x); as[1] = f2tf(aR0.y); as[2] = f2tf(aR0.z); as[3] = f2tf(aR0.w);
            as[4] = f2tf(aR1.x); as[5] = f2tf(aR1.y); as[6] = f2tf(aR1.z); as[7] = f2tf(aR1.w);
        }
        unsigned* bs = &Bs[buf][brow * BS_STRIDE + bcol];
        bs[0] = f2tf(bR0.x); bs[1] = f2tf(bR0.y); bs[2] = f2tf(bR0.z); bs[3] = f2tf(bR0.w);
        bs[4] = f2tf(bR1.x); bs[5] = f2tf(bR1.y); bs[6] = f2tf(bR1.z); bs[7] = f2tf(bR1.w);
        __syncthreads();
        if (kt + 16 < K) {
            if (AHALF) {
                aRh = aval ? *reinterpret_cast<const uint4*>(Aph + kt + 16)
                           : make_uint4(0, 0, 0, 0);
            } else {
                aR0 = aval ? *reinterpret_cast<const float4*>(Apf + kt + 16)
                           : make_float4(0, 0, 0, 0);
                aR1 = aval ? *reinterpret_cast<const float4*>(Apf + kt + 16 + 4)
                           : make_float4(0, 0, 0, 0);
            }
            bR0 = *reinterpret_cast<const float4*>(Bp + (size_t)(kt + 16) * N);
            bR1 = *reinterpret_cast<const float4*>(Bp + (size_t)(kt + 16) * N + 4);
        }
        #pragma unroll
        for (int ks = 0; ks < 2; ks++) {
            int k0 = ks * 8;
            unsigned a[2][4];
            #pragma unroll
            for (int mt = 0; mt < 2; mt++) {
                int r = rowBase + mt * 16 + g;
                a[mt][0] = As[buf][(r    ) * AS_STRIDE + k0 + tig];
                a[mt][1] = As[buf][(r + 8) * AS_STRIDE + k0 + tig];
                a[mt][2] = As[buf][(r    ) * AS_STRIDE + k0 + tig + 4];
                a[mt][3] = As[buf][(r + 8) * AS_STRIDE + k0 + tig + 4];
            }
            #pragma unroll
            for (int nt = 0; nt < 8; nt++) {
                int n = colBase + nt * 8 + g;
                unsigned b0 = Bs[buf][(k0 + tig    ) * BS_STRIDE + n];
                unsigned b1 = Bs[buf][(k0 + tig + 4) * BS_STRIDE + n];
                #pragma unroll
                for (int mt = 0; mt < 2; mt++)
                    mma_tf32(c[mt][nt][0], c[mt][nt][1], c[mt][nt][2], c[mt][nt][3],
                             a[mt][0], a[mt][1], a[mt][2], a[mt][3], b0, b1);
            }
        }
        buf ^= 1;
    }

    float*  Cf = (float*)Cvoid;
    __half* Ch = (__half*)Cvoid;
    #pragma unroll
    for (int mt = 0; mt < 2; mt++) {
        int r0 = row0 + rowBase + mt * 16 + g;   // and r0+8
        float p0 = 0.f, p1 = 0.f;
        #pragma unroll
        for (int nt = 0; nt < 8; nt++) {
            int col = col0 + colBase + nt * 8 + tig * 2;
            float o0 = c[mt][nt][0], o1 = c[mt][nt][1];
            float o2 = c[mt][nt][2], o3 = c[mt][nt][3];
            if (bias) {
                float bb0 = bias[col], bb1 = bias[col + 1];
                o0 = fmaxf(o0 + bb0, 0.f); o1 = fmaxf(o1 + bb1, 0.f);
                o2 = fmaxf(o2 + bb0, 0.f); o3 = fmaxf(o3 + bb1, 0.f);
            }
            if (OUTHALF) {
                __half2 ho = __floats2half2_rn(o0, o1);
                __half2 hp = __floats2half2_rn(o2, o3);
                if (r0 < M)
                    *reinterpret_cast<__half2*>(&Ch[(size_t)r0 * N + col]) = ho;
                if (r0 + 8 < M)
                    *reinterpret_cast<__half2*>(&Ch[(size_t)(r0 + 8) * N + col]) = hp;
            } else {
                if (r0 < M)
                    *reinterpret_cast<float2*>(&Cf[(size_t)r0 * N + col]) = make_float2(o0, o1);
                if (r0 + 8 < M)
                    *reinterpret_cast<float2*>(&Cf[(size_t)(r0 + 8) * N + col]) = make_float2(o2, o3);
            }
            if (Wa) {
                float w0 = Wa[col], w1 = Wa[col + 1];
                p0 = fmaf(o0, w0, fmaf(o1, w1, p0));
                p1 = fmaf(o2, w0, fmaf(o3, w1, p1));
            }
        }
        if (Wa) {
            p0 += __shfl_xor_sync(0xffffffffu, p0, 1);
            p0 += __shfl_xor_sync(0xffffffffu, p0, 2);
            p1 += __shfl_xor_sync(0xffffffffu, p1, 1);
            p1 += __shfl_xor_sync(0xffffffffu, p1, 2);
            if (tig == 0) {
                if (r0 < M)     atomicAdd(&g_logits[r0], p0);
                if (r0 + 8 < M) atomicAdd(&g_logits[r0 + 8], p1);
            }
        }
    }
}

// ---------------- softmax: global max (order-preserving encode) ----------------
__global__ void k_maxenc() {
    int i = blockIdx.x * blockDim.x + threadIdx.x;
    unsigned u = 0u;
    if (i < N_NODES) {
        unsigned b = __float_as_uint(g_logits[i]);
        u = (b & 0x80000000u) ? ~b : (b | 0x80000000u);
    }
    #pragma unroll
    for (int off = 16; off; off >>= 1) u = max(u, __shfl_xor_sync(0xffffffffu, u, off));
    if ((threadIdx.x & 31) == 0) atomicMax(&g_max_enc, u);
}

// ---------------- fused exp + weighted pool + wsum + finish --------------------
// 196 blocks; block b handles rows [b*256, b*256+256). Thread t = feature t.
__global__ __launch_bounds__(256) void k_pool(const float* __restrict__ h2,
                                              float* __restrict__ out_tail) {
    __shared__ float wsm[256];
    __shared__ bool amLast;
    int t = threadIdx.x;
    int r0 = blockIdx.x * 256;
    unsigned u = g_max_enc;
    float m = (u & 0x80000000u) ? __uint_as_float(u & 0x7FFFFFFFu) : __uint_as_float(~u);
    int r = r0 + t;
    float w = 0.f;
    if (r < N_NODES) w = expf(g_logits[r] - m);   // ONE expf per row
    wsm[t] = w;
    // block wsum: warp-reduce then one atomic
    float ws = w;
    #pragma unroll
    for (int off = 16; off; off >>= 1) ws += __shfl_xor_sync(0xffffffffu, ws, off);
    __syncthreads();
    if ((t & 31) == 0) atomicAdd(&g_wsum, ws);
    // weighted feature sum for feature f = t over this block's 256 rows
    int rend = min(r0 + 256, N_NODES);
    float acc = 0.f;
    for (int rr = r0; rr < rend; rr++)
        acc = fmaf(h2[(size_t)rr * OUT_DIM + t], wsm[rr - r0], acc);
    atomicAdd(&g_gacc[t], acc);
    __threadfence();
    if (t == 0) {
        unsigned done = atomicAdd(&g_poolctr, 1u);
        amLast = (done == gridDim.x - 1);
    }
    __syncthreads();
    if (amLast)
        out_tail[t] = __ldcg(&g_gacc[t]) / __ldcg(&g_wsum);
}

// ---------------- launch ----------------
extern "C" void kernel_launch(void* const* d_in, const int* in_sizes, int n_in,
                              void* d_out, int out_size) {
    const float* x  = (const float*)d_in[0];
    const void*  ei = d_in[1];
    const float* W1 = (const float*)d_in[2];
    const float* b1 = (const float*)d_in[3];
    const float* W2 = (const float*)d_in[4];
    const float* b2 = (const float*)d_in[5];
    const float* Wa = (const float*)d_in[6];
    float* out = (float*)d_out;

    float *bufA, *bufB;
    cudaGetSymbolAddress((void**)&bufA, g_bufA);
    cudaGetSymbolAddress((void**)&bufB, g_bufB);
    __half* hA = (__half*)bufA;
    __half* hB = (__half*)bufB;

    // one-time resources (created on the non-captured correctness call)
    static cudaStream_t s2 = nullptr;
    static cudaEvent_t evFork = nullptr, evJoin = nullptr;
    if (!s2) {
        cudaStreamCreateWithFlags(&s2, cudaStreamNonBlocking);
        cudaEventCreateWithFlags(&evFork, cudaEventDisableTiming);
        cudaEventCreateWithFlags(&evJoin, cudaEventDisableTiming);
    }

    // fork: CSR build on s2, GEMM1 (x@W1 -> fp16) on main stream
    cudaEventRecord(evFork, 0);
    cudaStreamWaitEvent(s2, evFork, 0);

    k_init<<<1, 256, 0, s2>>>((const int*)ei);
    k_count<<<(N_EDGES + 255) / 256, 256, 0, s2>>>(ei);
    k_scanA<<<NBLK, 256, 0, s2>>>();
    k_scanC<<<NBLK, 256, 0, s2>>>();
    k_fill<<<(N_EDGES + 255) / 256, 256, 0, s2>>>(ei);
    cudaEventRecord(evJoin, s2);

    {   // GEMM1 raw: hB = fp16(x @ W1)   (layer1 re-associated: relu(Agg(xW1)+b1))
        dim3 grid((N_NODES + 127) / 128, F_DIM / 128);
        k_gemm<false, true><<<grid, 256>>>(x, W1, nullptr, hB, N_NODES, F_DIM, nullptr);
    }
    cudaStreamWaitEvent(0, evJoin, 0);

    // layer 1 aggregation with fused bias+relu: hA = h1 (fp16)
    k_agg_h<<<(N_NODES * 32 + 255) / 256, 256>>>(hB, hA, b1);
    // layer 2: agg then GEMM (fp16 A) with bias+relu+fused logits -> fp32 out
    k_agg_h<<<(N_NODES * 32 + 255) / 256, 256>>>(hA, hB, nullptr);
    {
        dim3 grid((N_NODES + 127) / 128, OUT_DIM / 128);
        k_gemm<true, false><<<grid, 256>>>(hB, W2, b2, out, N_NODES, OUT_DIM, Wa);
    }
    // softmax-weighted pooling (exp + pool + finish fused)
    k_maxenc<<<NBLK, 256>>>();
    k_pool<<<NBLK, 256>>>(out, out + (size_t)N_NODES * OUT_DIM);
}

// round 14
// speedup vs baseline: 2.4621x; 1.0221x over previous
#include <cuda_runtime.h>
#include <cuda_fp16.h>
#include <math.h>

#define N_NODES 50000
#define N_EDGES 800000
#define F_DIM   128
#define OUT_DIM 256
#define NBLK    196   // ceil(50000/256)
#define MCHUNK  25000 // GEMM2/agg2 pipeline chunk

// ---------------- device scratch (no allocations allowed) ----------------
__device__ float    g_bufA[(size_t)N_NODES * F_DIM];   // reused as fp16
__device__ float    g_bufB[(size_t)N_NODES * F_DIM];
__device__ int      g_cnt[N_NODES];          // zero-init at load; re-zeroed by scanC
__device__ int      g_rowptr[N_NODES + 1];
__device__ int      g_cursor[N_NODES];
__device__ int      g_col[N_EDGES];
__device__ float    g_dinv[N_NODES];
__device__ float    g_logits[N_NODES];
__device__ int      g_part[NBLK];
__device__ unsigned g_max_enc;
__device__ float    g_wsum;
__device__ float    g_gacc[OUT_DIM];
__device__ unsigned g_poolctr;
__device__ int      g_is64;

// ---------------- helpers ----------------
__device__ __forceinline__ int edge_src(const void* ei, int e) {
    return g_is64 ? (int)((const long long*)ei)[e] : ((const int*)ei)[e];
}
__device__ __forceinline__ int edge_dst(const void* ei, int e) {
    return g_is64 ? (int)((const long long*)ei)[(size_t)N_EDGES + e]
                  : ((const int*)ei)[(size_t)N_EDGES + e];
}
__device__ __forceinline__ unsigned f2tf(float f) {
    unsigned r;
    asm("cvt.rna.tf32.f32 %0, %1;" : "=r"(r) : "f"(f));
    return r;
}
__device__ __forceinline__ void mma_tf32(float& c0, float& c1, float& c2, float& c3,
                                         unsigned a0, unsigned a1, unsigned a2, unsigned a3,
                                         unsigned b0, unsigned b1) {
    asm volatile("mma.sync.aligned.m16n8k8.row.col.f32.tf32.tf32.f32 "
                 "{%0,%1,%2,%3}, {%4,%5,%6,%7}, {%8,%9}, {%0,%1,%2,%3};"
                 : "+f"(c0), "+f"(c1), "+f"(c2), "+f"(c3)
                 : "r"(a0), "r"(a1), "r"(a2), "r"(a3), "r"(b0), "r"(b1));
}

// exclusive block scan of 256 ints, 2 syncthreads (warp shuffles + 8-wide fixup)
__device__ __forceinline__ int blockscan256_excl(int v, int t, int* wsum) {
    int lane = t & 31, w = t >> 5;
    int incl = v;
    #pragma unroll
    for (int off = 1; off < 32; off <<= 1) {
        int u = __shfl_up_sync(0xffffffffu, incl, off);
        if (lane >= off) incl += u;
    }
    if (lane == 31) wsum[w] = incl;
    __syncthreads();
    if (w == 0 && lane < 8) {
        int s = wsum[lane];
        #pragma unroll
        for (int off = 1; off < 8; off <<= 1) {
            int u = __shfl_up_sync(0xffu, s, off);
            if (lane >= off) s += u;
        }
        wsum[lane] = s;  // inclusive
    }
    __syncthreads();
    int base = (w > 0) ? wsum[w - 1] : 0;
    return base + incl - v;
}

// ---------------- init: scalars + gacc + dtype detect (1 block) ----------------
__global__ void k_init(const int* __restrict__ ei32) {
    g_gacc[threadIdx.x] = 0.f;
    if (threadIdx.x == 0) {
        g_wsum = 0.f; g_max_enc = 0u; g_poolctr = 0u;
        g_rowptr[N_NODES] = N_EDGES;
        int ornz = 0;
        #pragma unroll 8
        for (int k = 0; k < 256; k++) ornz |= ei32[2 * k + 1];
        g_is64 = (ornz == 0) ? 1 : 0;
    }
}

// ---------------- degree histogram ----------------
__global__ void k_count(const void* __restrict__ ei) {
    int e = blockIdx.x * blockDim.x + threadIdx.x;
    if (e >= N_EDGES) return;
    atomicAdd(&g_cnt[edge_dst(ei, e)], 1);
}

// ---------------- scanA: block sums + dinv + zero cursor/logits ----------------
__global__ void k_scanA() {
    __shared__ int sh[8];
    int t = threadIdx.x;
    int i = blockIdx.x * 256 + t;
    int v = (i < N_NODES) ? g_cnt[i] : 0;
    if (i < N_NODES) {
        g_dinv[i] = rsqrtf((float)(v + 1));  // +1 self-loop
        g_cursor[i] = 0;
        g_logits[i] = 0.f;
    }
    // block total via warp sums
    int s = v;
    #pragma unroll
    for (int off = 16; off; off >>= 1) s += __shfl_xor_sync(0xffffffffu, s, off);
    if ((t & 31) == 0) sh[t >> 5] = s;
    __syncthreads();
    if (t == 0) {
        int tot = 0;
        #pragma unroll
        for (int q = 0; q < 8; q++) tot += sh[q];
        g_part[blockIdx.x] = tot;
    }
}

// ---------------- scanC: rowptr (shuffle scans) + re-zero cnt ------------------
__global__ void k_scanC() {
    __shared__ int ws1[8];
    __shared__ int ws2[8];
    __shared__ int baseArr[256];
    int t = threadIdx.x;
    int pv = (t < NBLK) ? g_part[t] : 0;
    int pex = blockscan256_excl(pv, t, ws1);
    baseArr[t] = pex;
    int i = blockIdx.x * 256 + t;
    int v = (i < N_NODES) ? g_cnt[i] : 0;
    if (i < N_NODES) g_cnt[i] = 0;           // consumed — clean for next replay
    int vex = blockscan256_excl(v, t, ws2);  // includes the 2 syncthreads
    if (i < N_NODES) g_rowptr[i] = baseArr[blockIdx.x] + vex;
}

__global__ void k_fill(const void* __restrict__ ei) {
    int e = blockIdx.x * blockDim.x + threadIdx.x;
    if (e >= N_EDGES) return;
    int s = edge_src(ei, e);
    int d = edge_dst(ei, e);
    int pos = g_rowptr[d] + atomicAdd(&g_cursor[d], 1);
    g_col[pos] = s;
}

// ---------------- GCN aggregation (fp16): 2 nodes/warp, 16 lanes x uint4 -------
// out[i] = dinv_i * sum_j dinv_j*in[j] + dinv_i^2*in[i]  (+bias,relu optional)
__global__ void k_agg_h(const __half* __restrict__ in, __half* __restrict__ out,
                        const float* __restrict__ bias,
                        int node0, int nnodes) {
    int tid = blockIdx.x * blockDim.x + threadIdx.x;
    int node = node0 + (tid >> 4);            // 16 lanes per node
    if (node >= node0 + nnodes) return;
    int l16 = threadIdx.x & 15;
    const uint4* inv = reinterpret_cast<const uint4*>(in);  // row = 16 uint4
    float di = __ldg(&g_dinv[node]);
    uint4 raw = inv[(size_t)node * 16 + l16];
    float sw = di * di;
    float2 c0 = __half22float2(*reinterpret_cast<__half2*>(&raw.x));
    float2 c1 = __half22float2(*reinterpret_cast<__half2*>(&raw.y));
    float2 c2 = __half22float2(*reinterpret_cast<__half2*>(&raw.z));
    float2 c3 = __half22float2(*reinterpret_cast<__half2*>(&raw.w));
    float a0 = c0.x * sw, a1 = c0.y * sw, a2 = c1.x * sw, a3 = c1.y * sw;
    float a4 = c2.x * sw, a5 = c2.y * sw, a6 = c3.x * sw, a7 = c3.y * sw;
    int p = g_rowptr[node], end = g_rowptr[node + 1];
    for (; p + 4 <= end; p += 4) {
        int s[4]; uint4 rr[4]; float w[4];
        #pragma unroll
        for (int q = 0; q < 4; q++) s[q] = __ldg(&g_col[p + q]);
        #pragma unroll
        for (int q = 0; q < 4; q++) rr[q] = inv[(size_t)s[q] * 16 + l16];
        #pragma unroll
        for (int q = 0; q < 4; q++) w[q] = __ldg(&g_dinv[s[q]]) * di;
        #pragma unroll
        for (int q = 0; q < 4; q++) {
            float2 u0 = __half22float2(*reinterpret_cast<__half2*>(&rr[q].x));
            float2 u1 = __half22float2(*reinterpret_cast<__half2*>(&rr[q].y));
            float2 u2 = __half22float2(*reinterpret_cast<__half2*>(&rr[q].z));
            float2 u3 = __half22float2(*reinterpret_cast<__half2*>(&rr[q].w));
            a0 = fmaf(u0.x, w[q], a0); a1 = fmaf(u0.y, w[q], a1);
            a2 = fmaf(u1.x, w[q], a2); a3 = fmaf(u1.y, w[q], a3);
            a4 = fmaf(u2.x, w[q], a4); a5 = fmaf(u2.y, w[q], a5);
            a6 = fmaf(u3.x, w[q], a6); a7 = fmaf(u3.y, w[q], a7);
        }
    }
    for (; p < end; ++p) {
        int s = __ldg(&g_col[p]);
        float w = __ldg(&g_dinv[s]) * di;
        uint4 rr = inv[(size_t)s * 16 + l16];
        float2 u0 = __half22float2(*reinterpret_cast<__half2*>(&rr.x));
        float2 u1 = __half22float2(*reinterpret_cast<__half2*>(&rr.y));
        float2 u2 = __half22float2(*reinterpret_cast<__half2*>(&rr.z));
        float2 u3 = __half22float2(*reinterpret_cast<__half2*>(&rr.w));
        a0 = fmaf(u0.x, w, a0); a1 = fmaf(u0.y, w, a1);
        a2 = fmaf(u1.x, w, a2); a3 = fmaf(u1.y, w, a3);
        a4 = fmaf(u2.x, w, a4); a5 = fmaf(u2.y, w, a5);
        a6 = fmaf(u3.x, w, a6); a7 = fmaf(u3.y, w, a7);
    }
    if (bias) {
        const float4* bp = reinterpret_cast<const float4*>(bias) + l16 * 2;
        float4 bv0 = bp[0], bv1 = bp[1];
        a0 = fmaxf(a0 + bv0.x, 0.f); a1 = fmaxf(a1 + bv0.y, 0.f);
        a2 = fmaxf(a2 + bv0.z, 0.f); a3 = fmaxf(a3 + bv0.w, 0.f);
        a4 = fmaxf(a4 + bv1.x, 0.f); a5 = fmaxf(a5 + bv1.y, 0.f);
        a6 = fmaxf(a6 + bv1.z, 0.f); a7 = fmaxf(a7 + bv1.w, 0.f);
    }
    __half2 o0 = __floats2half2_rn(a0, a1), o1 = __floats2half2_rn(a2, a3);
    __half2 o2 = __floats2half2_rn(a4, a5), o3 = __floats2half2_rn(a6, a7);
    uint4 st;
    st.x = *reinterpret_cast<unsigned*>(&o0);
    st.y = *reinterpret_cast<unsigned*>(&o1);
    st.z = *reinterpret_cast<unsigned*>(&o2);
    st.w = *reinterpret_cast<unsigned*>(&o3);
    reinterpret_cast<uint4*>(out)[(size_t)node * 16 + l16] = st;
}

// ---------------- TF32 tensor-core GEMM (rowoff for global logit index) --------
#define AS_STRIDE 20
#define BS_STRIDE 136
template<bool AHALF, bool OUTHALF>
__global__ __launch_bounds__(256, 2) void k_gemm(
    const void* __restrict__ Avoid, const float* __restrict__ B,
    const float* __restrict__ bias, void* __restrict__ Cvoid, int M, int N,
    const float* __restrict__ Wa, int rowoff) {
    const int K = 128;
    __shared__ unsigned As[2][128 * AS_STRIDE];
    __shared__ unsigned Bs[2][16 * BS_STRIDE];

    int t = threadIdx.x;
    int lane = t & 31;
    int warp = t >> 5;
    int g = lane >> 2, tig = lane & 3;
    int row0 = blockIdx.x * 128;
    int col0 = blockIdx.y * 128;
    int warpM = warp & 3, warpN = warp >> 2;
    int rowBase = warpM * 32;
    int colBase = warpN * 64;

    int arow = t >> 1;
    int ahalf = (t & 1) * 8;
    int garow = row0 + arow;
    bool aval = garow < M;
    const float*  Apf = (const float*)Avoid + (size_t)garow * K + ahalf;
    const __half* Aph = (const __half*)Avoid + (size_t)garow * K + ahalf;
    int brow = t >> 4;
    int bcol = (t & 15) * 8;
    const float* Bp = B + (size_t)brow * N + col0 + bcol;

    float4 aR0, aR1;
    uint4 aRh;
    if (AHALF) {
        aRh = aval ? *reinterpret_cast<const uint4*>(Aph) : make_uint4(0, 0, 0, 0);
    } else {
        aR0 = aval ? *reinterpret_cast<const float4*>(Apf)     : make_float4(0, 0, 0, 0);
        aR1 = aval ? *reinterpret_cast<const float4*>(Apf + 4) : make_float4(0, 0, 0, 0);
    }
    float4 bR0 = *reinterpret_cast<const float4*>(Bp);
    float4 bR1 = *reinterpret_cast<const float4*>(Bp + 4);

    float c[2][8][4];
    #pragma unroll
    for (int i = 0; i < 2; i++)
        #pragma unroll
        for (int j = 0; j < 8; j++)
            #pragma unroll
            for (int q = 0; q < 4; q++) c[i][j][q] = 0.f;

    int buf = 0;
    for (int kt = 0; kt < K; kt += 16) {
        unsigned* as = &As[buf][arow * AS_STRIDE + ahalf];
        if (AHALF) {
            #pragma unroll
            for (int q = 0; q < 4; q++) {
                unsigned rw = (q == 0) ? aRh.x : (q == 1) ? aRh.y : (q == 2) ? aRh.z : aRh.w;
                float2 f = __half22float2(*reinterpret_cast<__half2*>(&rw));
                as[2 * q]     = __float_as_uint(f.x);
                as[2 * q + 1] = __float_as_uint(f.y);
            }
        } else {
            as[0] = f2tf(aR0.x); as[1] = f2tf(aR0.y); as[2] = f2tf(aR0.z); as[3] = f2tf(aR0.w);
            as[4] = f2tf(aR1.x); as[5] = f2tf(aR1.y); as[6] = f2tf(aR1.z); as[7] = f2tf(aR1.w);
        }
        unsigned* bs = &Bs[buf][brow * BS_STRIDE + bcol];
        bs[0] = f2tf(bR0.x); bs[1] = f2tf(bR0.y); bs[2] = f2tf(bR0.z); bs[3] = f2tf(bR0.w);
        bs[4] = f2tf(bR1.x); bs[5] = f2tf(bR1.y); bs[6] = f2tf(bR1.z); bs[7] = f2tf(bR1.w);
        __syncthreads();
        if (kt + 16 < K) {
            if (AHALF) {
                aRh = aval ? *reinterpret_cast<const uint4*>(Aph + kt + 16)
                           : make_uint4(0, 0, 0, 0);
            } else {
                aR0 = aval ? *reinterpret_cast<const float4*>(Apf + kt + 16)
                           : make_float4(0, 0, 0, 0);
                aR1 = aval ? *reinterpret_cast<const float4*>(Apf + kt + 16 + 4)
                           : make_float4(0, 0, 0, 0);
            }
            bR0 = *reinterpret_cast<const float4*>(Bp + (size_t)(kt + 16) * N);
            bR1 = *reinterpret_cast<const float4*>(Bp + (size_t)(kt + 16) * N + 4);
        }
        #pragma unroll
        for (int ks = 0; ks < 2; ks++) {
            int k0 = ks * 8;
            unsigned a[2][4];
            #pragma unroll
            for (int mt = 0; mt < 2; mt++) {
                int r = rowBase + mt * 16 + g;
                a[mt][0] = As[buf][(r    ) * AS_STRIDE + k0 + tig];
                a[mt][1] = As[buf][(r + 8) * AS_STRIDE + k0 + tig];
                a[mt][2] = As[buf][(r    ) * AS_STRIDE + k0 + tig + 4];
                a[mt][3] = As[buf][(r + 8) * AS_STRIDE + k0 + tig + 4];
            }
            #pragma unroll
            for (int nt = 0; nt < 8; nt++) {
                int n = colBase + nt * 8 + g;
                unsigned b0 = Bs[buf][(k0 + tig    ) * BS_STRIDE + n];
                unsigned b1 = Bs[buf][(k0 + tig + 4) * BS_STRIDE + n];
                #pragma unroll
                for (int mt = 0; mt < 2; mt++)
                    mma_tf32(c[mt][nt][0], c[mt][nt][1], c[mt][nt][2], c[mt][nt][3],
                             a[mt][0], a[mt][1], a[mt][2], a[mt][3], b0, b1);
            }
        }
        buf ^= 1;
    }

    float*  Cf = (float*)Cvoid;
    __half* Ch = (__half*)Cvoid;
    #pragma unroll
    for (int mt = 0; mt < 2; mt++) {
        int r0 = row0 + rowBase + mt * 16 + g;   // chunk-local; and r0+8
        float p0 = 0.f, p1 = 0.f;
        #pragma unroll
        for (int nt = 0; nt < 8; nt++) {
            int col = col0 + colBase + nt * 8 + tig * 2;
            float o0 = c[mt][nt][0], o1 = c[mt][nt][1];
            float o2 = c[mt][nt][2], o3 = c[mt][nt][3];
            if (bias) {
                float bb0 = bias[col], bb1 = bias[col + 1];
                o0 = fmaxf(o0 + bb0, 0.f); o1 = fmaxf(o1 + bb1, 0.f);
                o2 = fmaxf(o2 + bb0, 0.f); o3 = fmaxf(o3 + bb1, 0.f);
            }
            if (OUTHALF) {
                __half2 ho = __floats2half2_rn(o0, o1);
                __half2 hp = __floats2half2_rn(o2, o3);
                if (r0 < M)
                    *reinterpret_cast<__half2*>(&Ch[(size_t)r0 * N + col]) = ho;
                if (r0 + 8 < M)
                    *reinterpret_cast<__half2*>(&Ch[(size_t)(r0 + 8) * N + col]) = hp;
            } else {
                if (r0 < M)
                    *reinterpret_cast<float2*>(&Cf[(size_t)r0 * N + col]) = make_float2(o0, o1);
                if (r0 + 8 < M)
                    *reinterpret_cast<float2*>(&Cf[(size_t)(r0 + 8) * N + col]) = make_float2(o2, o3);
            }
            if (Wa) {
                float w0 = Wa[col], w1 = Wa[col + 1];
                p0 = fmaf(o0, w0, fmaf(o1, w1, p0));
                p1 = fmaf(o2, w0, fmaf(o3, w1, p1));
            }
        }
        if (Wa) {
            p0 += __shfl_xor_sync(0xffffffffu, p0, 1);
            p0 += __shfl_xor_sync(0xffffffffu, p0, 2);
            p1 += __shfl_xor_sync(0xffffffffu, p1, 1);
            p1 += __shfl_xor_sync(0xffffffffu, p1, 2);
            if (tig == 0) {
                if (r0 < M)     atomicAdd(&g_logits[rowoff + r0], p0);
                if (r0 + 8 < M) atomicAdd(&g_logits[rowoff + r0 + 8], p1);
            }
        }
    }
}

// ---------------- softmax: global max (order-preserving encode) ----------------
__global__ void k_maxenc() {
    int i = blockIdx.x * blockDim.x + threadIdx.x;
    unsigned u = 0u;
    if (i < N_NODES) {
        unsigned b = __float_as_uint(g_logits[i]);
        u = (b & 0x80000000u) ? ~b : (b | 0x80000000u);
    }
    #pragma unroll
    for (int off = 16; off; off >>= 1) u = max(u, __shfl_xor_sync(0xffffffffu, u, off));
    if ((threadIdx.x & 31) == 0) atomicMax(&g_max_enc, u);
}

// ---------------- fused exp + weighted pool + wsum + finish --------------------
__global__ __launch_bounds__(256) void k_pool(const float* __restrict__ h2,
                                              float* __restrict__ out_tail) {
    __shared__ float wsm[256];
    __shared__ bool amLast;
    int t = threadIdx.x;
    int r0 = blockIdx.x * 256;
    unsigned u = g_max_enc;
    float m = (u & 0x80000000u) ? __uint_as_float(u & 0x7FFFFFFFu) : __uint_as_float(~u);
    int r = r0 + t;
    float w = 0.f;
    if (r < N_NODES) w = expf(g_logits[r] - m);
    wsm[t] = w;
    float ws = w;
    #pragma unroll
    for (int off = 16; off; off >>= 1) ws += __shfl_xor_sync(0xffffffffu, ws, off);
    __syncthreads();
    if ((t & 31) == 0) atomicAdd(&g_wsum, ws);
    int rend = min(r0 + 256, N_NODES);
    float acc = 0.f;
    for (int rr = r0; rr < rend; rr++)
        acc = fmaf(h2[(size_t)rr * OUT_DIM + t], wsm[rr - r0], acc);
    atomicAdd(&g_gacc[t], acc);
    __threadfence();
    if (t == 0) {
        unsigned done = atomicAdd(&g_poolctr, 1u);
        amLast = (done == gridDim.x - 1);
    }
    __syncthreads();
    if (amLast)
        out_tail[t] = __ldcg(&g_gacc[t]) / __ldcg(&g_wsum);
}

// ---------------- launch ----------------
extern "C" void kernel_launch(void* const* d_in, const int* in_sizes, int n_in,
                              void* d_out, int out_size) {
    const float* x  = (const float*)d_in[0];
    const void*  ei = d_in[1];
    const float* W1 = (const float*)d_in[2];
    const float* b1 = (const float*)d_in[3];
    const float* W2 = (const float*)d_in[4];
    const float* b2 = (const float*)d_in[5];
    const float* Wa = (const float*)d_in[6];
    float* out = (float*)d_out;

    float *bufA, *bufB;
    cudaGetSymbolAddress((void**)&bufA, g_bufA);
    cudaGetSymbolAddress((void**)&bufB, g_bufB);
    __half* hA = (__half*)bufA;
    __half* hB = (__half*)bufB;

    static cudaStream_t s2 = nullptr;
    static cudaEvent_t evFork = nullptr, evJoin = nullptr;
    static cudaEvent_t evA0 = nullptr, evA1 = nullptr, evG2 = nullptr;
    if (!s2) {
        cudaStreamCreateWithFlags(&s2, cudaStreamNonBlocking);
        cudaEventCreateWithFlags(&evFork, cudaEventDisableTiming);
        cudaEventCreateWithFlags(&evJoin, cudaEventDisableTiming);
        cudaEventCreateWithFlags(&evA0, cudaEventDisableTiming);
        cudaEventCreateWithFlags(&evA1, cudaEventDisableTiming);
        cudaEventCreateWithFlags(&evG2, cudaEventDisableTiming);
    }

    const int AGG_TPB = 256;                 // 16 nodes per block
    const int aggBlocksFull  = (N_NODES * 16 + AGG_TPB - 1) / AGG_TPB;
    const int aggBlocksChunk = (MCHUNK * 16 + AGG_TPB - 1) / AGG_TPB;

    // fork: CSR build on s2, GEMM1 (x@W1 -> fp16) on main stream
    cudaEventRecord(evFork, 0);
    cudaStreamWaitEvent(s2, evFork, 0);

    k_init<<<1, 256, 0, s2>>>((const int*)ei);
    k_count<<<(N_EDGES + 255) / 256, 256, 0, s2>>>(ei);
    k_scanA<<<NBLK, 256, 0, s2>>>();
    k_scanC<<<NBLK, 256, 0, s2>>>();
    k_fill<<<(N_EDGES + 255) / 256, 256, 0, s2>>>(ei);
    cudaEventRecord(evJoin, s2);

    {   // GEMM1 raw: hB = fp16(x @ W1)   (layer1 re-associated: relu(Agg(xW1)+b1))
        dim3 grid((N_NODES + 127) / 128, F_DIM / 128);
        k_gemm<false, true><<<grid, 256>>>(x, W1, nullptr, hB, N_NODES, F_DIM, nullptr, 0);
    }
    cudaStreamWaitEvent(0, evJoin, 0);

    // layer 1 aggregation with fused bias+relu: hA = h1 (fp16)
    k_agg_h<<<aggBlocksFull, AGG_TPB>>>(hB, hA, b1, 0, N_NODES);

    // layer 2 pipelined: agg2 chunk c on main, GEMM2 chunk c on s2
    dim3 grid2((MCHUNK + 127) / 128, OUT_DIM / 128);
    k_agg_h<<<aggBlocksChunk, AGG_TPB>>>(hA, hB, nullptr, 0, MCHUNK);
    cudaEventRecord(evA0, 0);
    k_agg_h<<<aggBlocksChunk, AGG_TPB>>>(hA, hB, nullptr, MCHUNK, N_NODES - MCHUNK);
    cudaEventRecord(evA1, 0);

    cudaStreamWaitEvent(s2, evA0, 0);
    k_gemm<true, false><<<grid2, 256, 0, s2>>>(
        hB, W2, b2, out, MCHUNK, OUT_DIM, Wa, 0);
    cudaStreamWaitEvent(s2, evA1, 0);
    k_gemm<true, false><<<grid2, 256, 0, s2>>>(
        hB + (size_t)MCHUNK * F_DIM, W2, b2, out + (size_t)MCHUNK * OUT_DIM,
        N_NODES - MCHUNK, OUT_DIM, Wa, MCHUNK);
    cudaEventRecord(evG2, s2);
    cudaStreamWaitEvent(0, evG2, 0);

    // softmax-weighted pooling (exp + pool + finish fused)
    k_maxenc<<<NBLK, 256>>>();
    k_pool<<<NBLK, 256>>>(out, out + (size_t)N_NODES * OUT_DIM);
}